// round 9
// baseline (speedup 1.0000x reference)
#include <cuda_runtime.h>
#include <math.h>

constexpr int T   = 2048;
constexpr int H   = 1024;
constexpr int NH  = 16;
constexpr int NKV = 4;
constexpr int HD  = 64;
constexpr int NE  = 8;
constexpr int F   = 2048;
constexpr int QKVN = (NH + 2 * NKV) * HD;  // 1536
constexpr float EPS = 1e-5f;

// ---- scratch: device globals, referenced ONLY inside device code ----------
// (passing them as host-side kernel args resolves to the host shadow symbol,
//  which GB300's ATS silently dereferences into host RAM — the round<=8 bug)
__device__ float g_xnorm[T * H];
__device__ float g_qkv[T * QKVN];
__device__ float g_attn[T * NH * HD];
__device__ float g_x1[T * H];
__device__ float g_xnorm2[T * H];
__device__ int   g_cnt[NE];
__device__ int   g_ptok[NE * T];
__device__ int   g_slot[2 * T];
__device__ float g_gatew[2 * T];
__device__ float g_act[NE * T * F];
__device__ float g_y[NE * T * H];
__device__ int   g_mask;

// ---------------------------------------------------------------- utilities
__device__ __forceinline__ float block_sum_256(float v) {
    __shared__ float red[8];
    #pragma unroll
    for (int o = 16; o; o >>= 1) v += __shfl_xor_sync(0xffffffffu, v, o);
    if ((threadIdx.x & 31) == 0) red[threadIdx.x >> 5] = v;
    __syncthreads();
    if (threadIdx.x == 0) {
        float s = 0.f;
        #pragma unroll
        for (int i = 0; i < 8; i++) s += red[i];
        red[0] = s;
    }
    __syncthreads();
    float r = red[0];
    __syncthreads();
    return r;
}

// ------------------------------------------------------------------ kernels
__global__ void zero_cnt_kernel() {
    if (threadIdx.x < NE) g_cnt[threadIdx.x] = 0;
    if (threadIdx.x == 0) g_mask = 0;
}

// MODE 0: x = xin(arg hidden), out = g_xnorm ; MODE 1: x = g_x1, out = g_xnorm2
template <int MODE>
__global__ __launch_bounds__(256) void rmsnorm_kernel(
    const float* __restrict__ xin, const float* __restrict__ w)
{
    int t = blockIdx.x;
    const float* x = (MODE == 0) ? xin : (const float*)g_x1;
    float* out = (MODE == 0) ? g_xnorm : g_xnorm2;
    const float* xr = x + (size_t)t * H;
    float ss = 0.f;
    for (int i = threadIdx.x; i < H; i += 256) { float v = xr[i]; ss += v * v; }
    float tot = block_sum_256(ss);
    float scale = rsqrtf(tot / (float)H + EPS);
    for (int i = threadIdx.x; i < H; i += 256)
        out[(size_t)t * H + i] = xr[i] * scale * w[i];
}

// MODE 0: C=g_qkv  = g_xnorm * B^T (N=QKVN). MODE 1: C=g_x1 = g_attn * B^T + resid (N=H)
template <int MODE>
__global__ __launch_bounds__(256) void gemm_kernel(
    const float* __restrict__ B, const float* __restrict__ resid)
{
    constexpr int K = H;
    constexpr int N = (MODE == 0) ? QKVN : H;
    const float* A = (MODE == 0) ? (const float*)g_xnorm : (const float*)g_attn;
    float* C = (MODE == 0) ? g_qkv : g_x1;

    __shared__ float As[64][16];
    __shared__ float Bs[16][64];
    int tid = threadIdx.x;
    int tx = tid & 15, ty = tid >> 4;
    int lrow = tid >> 2, lk4 = (tid & 3) << 2;
    int n0 = blockIdx.x * 64, m0 = blockIdx.y * 64;

    const float* Ap = A + (size_t)(m0 + lrow) * K + lk4;
    const float* Bp = B + (size_t)(n0 + lrow) * K + lk4;

    float acc[4][4] = {};
    for (int k0 = 0; k0 < K; k0 += 16) {
        float4 av = *(const float4*)(Ap + k0);
        float4 bv = *(const float4*)(Bp + k0);
        *(float4*)&As[lrow][lk4] = av;
        Bs[lk4 + 0][lrow] = bv.x; Bs[lk4 + 1][lrow] = bv.y;
        Bs[lk4 + 2][lrow] = bv.z; Bs[lk4 + 3][lrow] = bv.w;
        __syncthreads();
        #pragma unroll
        for (int k = 0; k < 16; k++) {
            float4 b = *(const float4*)&Bs[k][tx * 4];
            float a0 = As[ty * 4 + 0][k], a1 = As[ty * 4 + 1][k];
            float a2 = As[ty * 4 + 2][k], a3 = As[ty * 4 + 3][k];
            acc[0][0] += a0 * b.x; acc[0][1] += a0 * b.y; acc[0][2] += a0 * b.z; acc[0][3] += a0 * b.w;
            acc[1][0] += a1 * b.x; acc[1][1] += a1 * b.y; acc[1][2] += a1 * b.z; acc[1][3] += a1 * b.w;
            acc[2][0] += a2 * b.x; acc[2][1] += a2 * b.y; acc[2][2] += a2 * b.z; acc[2][3] += a2 * b.w;
            acc[3][0] += a3 * b.x; acc[3][1] += a3 * b.y; acc[3][2] += a3 * b.z; acc[3][3] += a3 * b.w;
        }
        __syncthreads();
    }
    #pragma unroll
    for (int i = 0; i < 4; i++) {
        int m = m0 + ty * 4 + i;
        #pragma unroll
        for (int j = 0; j < 4; j++) {
            int n = n0 + tx * 4 + j;
            float v = acc[i][j];
            if (MODE == 1) v += resid[(size_t)m * N + n];
            C[(size_t)m * N + n] = v;
        }
    }
}

__global__ void rope_kernel(const int* __restrict__ pos) {
    int t = blockIdx.x;
    int h = threadIdx.x >> 5, d = threadIdx.x & 31;
    float p = (float)pos[t];
    float inv = powf(10000.f, -(float)d / 32.f);
    float ang = p * inv;
    float c, s;
    sincosf(ang, &s, &c);
    float* base = g_qkv + (size_t)t * QKVN + h * HD;
    float x1 = base[d], x2 = base[d + 32];
    base[d]      = x1 * c - x2 * s;
    base[d + 32] = x2 * c + x1 * s;
}

__global__ __launch_bounds__(256) void attn_kernel() {
    __shared__ float Qs[32][65];
    __shared__ float KVs[64][65];
    __shared__ float Ps[32][65];
    int qt = blockIdx.x, h = blockIdx.y;
    int q0 = qt * 32;
    int kvh = h >> 2;
    int tid = threadIdx.x, tx = tid & 15, ty = tid >> 4;

    #pragma unroll
    for (int it = 0; it < 2; it++) {
        int idx = it * 256 + tid;
        int r = idx >> 4, dc = (idx & 15) << 2;
        float4 v = *(const float4*)(g_qkv + (size_t)(q0 + r) * QKVN + h * HD + dc);
        Qs[r][dc] = v.x; Qs[r][dc + 1] = v.y; Qs[r][dc + 2] = v.z; Qs[r][dc + 3] = v.w;
    }

    float m_i[2] = {-1e30f, -1e30f};
    float l_i[2] = {0.f, 0.f};
    float O[2][4] = {};
    int ktmax = qt >> 1;

    for (int kt = 0; kt <= ktmax; kt++) {
        int k0 = kt * 64;
        bool lastt = (kt == ktmax);
        __syncthreads();
        #pragma unroll
        for (int it = 0; it < 4; it++) {
            int idx = it * 256 + tid;
            int r = idx >> 4, dc = (idx & 15) << 2;
            float4 v = *(const float4*)(g_qkv + (size_t)(k0 + r) * QKVN + 1024 + kvh * HD + dc);
            KVs[r][dc] = v.x; KVs[r][dc + 1] = v.y; KVs[r][dc + 2] = v.z; KVs[r][dc + 3] = v.w;
        }
        __syncthreads();

        float sv[2][4] = {};
        #pragma unroll 16
        for (int d = 0; d < 64; d++) {
            float q0r = Qs[2 * ty + 0][d];
            float q1r = Qs[2 * ty + 1][d];
            #pragma unroll
            for (int j = 0; j < 4; j++) {
                float kv = KVs[4 * tx + j][d];
                sv[0][j] += q0r * kv;
                sv[1][j] += q1r * kv;
            }
        }
        #pragma unroll
        for (int i = 0; i < 2; i++) {
            int qrow = q0 + 2 * ty + i;
            float p[4], mx = -1e30f;
            #pragma unroll
            for (int j = 0; j < 4; j++) {
                float s = sv[i][j] * 0.125f;
                if (lastt && (k0 + 4 * tx + j > qrow)) s = -1e30f;
                p[j] = s;
                mx = fmaxf(mx, s);
            }
            #pragma unroll
            for (int o = 8; o; o >>= 1) mx = fmaxf(mx, __shfl_xor_sync(0xffffffffu, mx, o));
            float mnew = fmaxf(m_i[i], mx);
            float rs = 0.f;
            #pragma unroll
            for (int j = 0; j < 4; j++) { p[j] = __expf(p[j] - mnew); rs += p[j]; }
            #pragma unroll
            for (int o = 8; o; o >>= 1) rs += __shfl_xor_sync(0xffffffffu, rs, o);
            float fac = __expf(m_i[i] - mnew);
            l_i[i] = l_i[i] * fac + rs;
            m_i[i] = mnew;
            #pragma unroll
            for (int j = 0; j < 4; j++) O[i][j] *= fac;
            #pragma unroll
            for (int j = 0; j < 4; j++) Ps[2 * ty + i][4 * tx + j] = p[j];
        }
        __syncthreads();
        #pragma unroll
        for (int it = 0; it < 4; it++) {
            int idx = it * 256 + tid;
            int r = idx >> 4, dc = (idx & 15) << 2;
            float4 v = *(const float4*)(g_qkv + (size_t)(k0 + r) * QKVN + 1280 + kvh * HD + dc);
            KVs[r][dc] = v.x; KVs[r][dc + 1] = v.y; KVs[r][dc + 2] = v.z; KVs[r][dc + 3] = v.w;
        }
        __syncthreads();
        #pragma unroll 16
        for (int k = 0; k < 64; k++) {
            float p0 = Ps[2 * ty + 0][k];
            float p1 = Ps[2 * ty + 1][k];
            #pragma unroll
            for (int j = 0; j < 4; j++) {
                float vv = KVs[k][4 * tx + j];
                O[0][j] += p0 * vv;
                O[1][j] += p1 * vv;
            }
        }
    }
    #pragma unroll
    for (int i = 0; i < 2; i++) {
        float inv = 1.f / l_i[i];
        int qrow = q0 + 2 * ty + i;
        #pragma unroll
        for (int j = 0; j < 4; j++)
            g_attn[(size_t)qrow * (NH * HD) + h * HD + 4 * tx + j] = O[i][j] * inv;
    }
}

__global__ __launch_bounds__(256) void gate_kernel(const float* __restrict__ gate_w) {
    int t = blockIdx.x;
    const float* x = g_xnorm2 + (size_t)t * H;
    int w = threadIdx.x >> 5, lane = threadIdx.x & 31;
    float s = 0.f;
    const float* gw = gate_w + (size_t)w * H;
    for (int i = lane; i < H; i += 32) s += x[i] * gw[i];
    #pragma unroll
    for (int o = 16; o; o >>= 1) s += __shfl_xor_sync(0xffffffffu, s, o);
    __shared__ float logits[NE];
    if (lane == 0) logits[w] = s;
    __syncthreads();
    if (threadIdx.x == 0) {
        float mx = logits[0];
        #pragma unroll
        for (int e = 1; e < NE; e++) mx = fmaxf(mx, logits[e]);
        float p[NE];
        #pragma unroll
        for (int e = 0; e < NE; e++) p[e] = __expf(logits[e] - mx);
        int i1 = 0;
        #pragma unroll
        for (int e = 1; e < NE; e++) if (p[e] > p[i1]) i1 = e;
        int i2 = (i1 == 0) ? 1 : 0;
        #pragma unroll
        for (int e = 0; e < NE; e++) if (e != i1 && p[e] > p[i2]) i2 = e;
        float inv = 1.f / (p[i1] + p[i2]);
        int s0 = atomicAdd(&g_cnt[i1], 1);
        g_ptok[i1 * T + s0] = t;
        g_slot[2 * t + 0] = i1 * T + s0;
        g_gatew[2 * t + 0] = p[i1] * inv;
        int s1 = atomicAdd(&g_cnt[i2], 1);
        g_ptok[i2 * T + s1] = t;
        g_slot[2 * t + 1] = i2 * T + s1;
        g_gatew[2 * t + 1] = p[i2] * inv;
    }
}

__global__ __launch_bounds__(256) void moe_gemm1(
    const float* __restrict__ W1, const float* __restrict__ W3)
{
    int e = blockIdx.z;
    int cnt = g_cnt[e];
    int m0 = blockIdx.y * 64;
    if (m0 >= cnt) return;
    int n0 = blockIdx.x * 64;

    __shared__ float As[64][16];
    __shared__ float B1s[16][64];
    __shared__ float B3s[16][64];
    __shared__ int toks[64];

    int tid = threadIdx.x, tx = tid & 15, ty = tid >> 4;
    int lrow = tid >> 2, lk4 = (tid & 3) << 2;
    if (tid < 64) {
        int s = m0 + tid;
        toks[tid] = (s < cnt) ? g_ptok[e * T + s] : 0;
    }
    __syncthreads();

    const float* W1e = W1 + (size_t)e * F * H + (size_t)(n0 + lrow) * H + lk4;
    const float* W3e = W3 + (size_t)e * F * H + (size_t)(n0 + lrow) * H + lk4;
    const float* Ap = g_xnorm2 + (size_t)toks[lrow] * H + lk4;

    float acc1[4][4] = {}, acc3[4][4] = {};
    for (int k0 = 0; k0 < H; k0 += 16) {
        float4 av = *(const float4*)(Ap + k0);
        float4 b1 = *(const float4*)(W1e + k0);
        float4 b3 = *(const float4*)(W3e + k0);
        *(float4*)&As[lrow][lk4] = av;
        B1s[lk4 + 0][lrow] = b1.x; B1s[lk4 + 1][lrow] = b1.y;
        B1s[lk4 + 2][lrow] = b1.z; B1s[lk4 + 3][lrow] = b1.w;
        B3s[lk4 + 0][lrow] = b3.x; B3s[lk4 + 1][lrow] = b3.y;
        B3s[lk4 + 2][lrow] = b3.z; B3s[lk4 + 3][lrow] = b3.w;
        __syncthreads();
        #pragma unroll
        for (int k = 0; k < 16; k++) {
            float4 bb1 = *(const float4*)&B1s[k][tx * 4];
            float4 bb3 = *(const float4*)&B3s[k][tx * 4];
            #pragma unroll
            for (int i = 0; i < 4; i++) {
                float a = As[ty * 4 + i][k];
                acc1[i][0] += a * bb1.x; acc1[i][1] += a * bb1.y;
                acc1[i][2] += a * bb1.z; acc1[i][3] += a * bb1.w;
                acc3[i][0] += a * bb3.x; acc3[i][1] += a * bb3.y;
                acc3[i][2] += a * bb3.z; acc3[i][3] += a * bb3.w;
            }
        }
        __syncthreads();
    }
    #pragma unroll
    for (int i = 0; i < 4; i++) {
        int s = m0 + ty * 4 + i;
        if (s >= cnt) continue;
        float* dst = g_act + (size_t)(e * T + s) * F + n0 + tx * 4;
        #pragma unroll
        for (int j = 0; j < 4; j++) {
            float h1 = acc1[i][j];
            float sig = 1.f / (1.f + __expf(-h1));
            dst[j] = h1 * sig * acc3[i][j];
        }
    }
}

__global__ __launch_bounds__(256) void moe_gemm2(const float* __restrict__ W2) {
    int e = blockIdx.z;
    int cnt = g_cnt[e];
    int m0 = blockIdx.y * 64;
    if (m0 >= cnt) return;
    int n0 = blockIdx.x * 64;

    __shared__ float As[64][16];
    __shared__ float Bs[16][64];
    int tid = threadIdx.x, tx = tid & 15, ty = tid >> 4;
    int lrow = tid >> 2, lk4 = (tid & 3) << 2;

    const float* Ap = g_act + (size_t)(e * T + m0 + lrow) * F + lk4;
    const float* Bp = W2 + (size_t)e * H * F + (size_t)(n0 + lrow) * F + lk4;

    float acc[4][4] = {};
    for (int k0 = 0; k0 < F; k0 += 16) {
        float4 av = *(const float4*)(Ap + k0);
        float4 bv = *(const float4*)(Bp + k0);
        *(float4*)&As[lrow][lk4] = av;
        Bs[lk4 + 0][lrow] = bv.x; Bs[lk4 + 1][lrow] = bv.y;
        Bs[lk4 + 2][lrow] = bv.z; Bs[lk4 + 3][lrow] = bv.w;
        __syncthreads();
        #pragma unroll
        for (int k = 0; k < 16; k++) {
            float4 b = *(const float4*)&Bs[k][tx * 4];
            float a0 = As[ty * 4 + 0][k], a1 = As[ty * 4 + 1][k];
            float a2 = As[ty * 4 + 2][k], a3 = As[ty * 4 + 3][k];
            acc[0][0] += a0 * b.x; acc[0][1] += a0 * b.y; acc[0][2] += a0 * b.z; acc[0][3] += a0 * b.w;
            acc[1][0] += a1 * b.x; acc[1][1] += a1 * b.y; acc[1][2] += a1 * b.z; acc[1][3] += a1 * b.w;
            acc[2][0] += a2 * b.x; acc[2][1] += a2 * b.y; acc[2][2] += a2 * b.z; acc[2][3] += a2 * b.w;
            acc[3][0] += a3 * b.x; acc[3][1] += a3 * b.y; acc[3][2] += a3 * b.z; acc[3][3] += a3 * b.w;
        }
        __syncthreads();
    }
    #pragma unroll
    for (int i = 0; i < 4; i++) {
        int s = m0 + ty * 4 + i;
        if (s >= cnt) continue;
        float* dst = g_y + (size_t)(e * T + s) * H + n0 + tx * 4;
        #pragma unroll
        for (int j = 0; j < 4; j++) dst[j] = acc[i][j];
    }
}

// -------- slim single-thread verifier; failures set bits in g_mask ---------
__device__ __forceinline__ bool chk(float got, float ref) {
    return fabsf(got - ref) <= 2e-2f * (fabsf(ref) + 1e-3f);
}

__global__ void selfcheck_kernel(const float* hidden, const float* w_qkv,
                                 const float* w_o,
                                 const float* w1, const float* w2, const float* w3)
{
    if (threadIdx.x != 0 || blockIdx.x != 0) return;
    int mask = 0;
    // 1: rmsnorm1
    {
        float ss = 0.f;
        for (int i = 0; i < H; i++) ss += hidden[i] * hidden[i];
        float sc = rsqrtf(ss / (float)H + EPS);
        if (!chk(g_xnorm[0], hidden[0] * sc)) mask |= 1;
    }
    // 2: qkv v00
    {
        float dv = 0.f;
        for (int k = 0; k < H; k++) dv += g_xnorm[k] * w_qkv[(size_t)1280 * H + k];
        if (!chk(g_qkv[1280], dv)) mask |= 2;
    }
    // 4: attn token 0 == own V
    if (!chk(g_attn[0], g_qkv[1280])) mask |= 4;
    // 8: o-proj + residual
    {
        float xo = 0.f;
        for (int k = 0; k < NH * HD; k++) xo += g_attn[k] * w_o[k];
        if (!chk(g_x1[0], hidden[0] + xo)) mask |= 8;
    }
    // 16: rmsnorm2
    {
        float ss = 0.f;
        for (int i = 0; i < H; i++) ss += g_x1[i] * g_x1[i];
        float sc = rsqrtf(ss / (float)H + EPS);
        if (!chk(g_xnorm2[0], g_x1[0] * sc)) mask |= 16;
    }
    // 128: routing sanity; 32: act; 64: y
    {
        int tot = 0;
        for (int e = 0; e < NE; e++) tot += g_cnt[e];
        int s0 = g_slot[0];
        if (tot != 2 * T || s0 < 0 || s0 >= NE * T || g_ptok[s0] != 0) mask |= 128;
        else {
            int e0 = s0 / T;
            float a1 = 0.f, a3 = 0.f;
            for (int k = 0; k < H; k++) {
                a1 += g_xnorm2[k] * w1[(size_t)e0 * F * H + k];
                a3 += g_xnorm2[k] * w3[(size_t)e0 * F * H + k];
            }
            float actref = a1 / (1.f + __expf(-a1)) * a3;
            if (!chk(g_act[(size_t)s0 * F], actref)) mask |= 32;
            float y0 = 0.f;
            for (int f = 0; f < F; f++)
                y0 += g_act[(size_t)s0 * F + f] * w2[(size_t)e0 * H * F + f];
            if (!chk(g_y[(size_t)s0 * H], y0)) mask |= 64;
        }
    }
    g_mask = mask;
}

// x = x1 + g0*y0 + g1*y1; rmsnorm(x) -> out[0..T*H); x -> out[T*H..) if room.
__global__ __launch_bounds__(256) void combine_kernel(
    const float* __restrict__ w_next, float* __restrict__ out, int write_x)
{
    __shared__ float xs[H];
    int t = blockIdx.x;
    int mask = g_mask;
    int s0 = g_slot[2 * t + 0], s1 = g_slot[2 * t + 1];
    float g0 = g_gatew[2 * t + 0], g1 = g_gatew[2 * t + 1];
    float ss = 0.f;
    for (int i = threadIdx.x; i < H; i += 256) {
        float v = g_x1[(size_t)t * H + i]
                + g0 * g_y[(size_t)s0 * H + i]
                + g1 * g_y[(size_t)s1 * H + i];
        xs[i] = v;
        if (write_x) out[(size_t)T * H + (size_t)t * H + i] = v;
        ss += v * v;
    }
    float tot = block_sum_256(ss);
    float scale = rsqrtf(tot / (float)H + EPS);
    __syncthreads();
    for (int i = threadIdx.x; i < H; i += 256) {
        float v = xs[i] * scale * w_next[i];
        out[(size_t)t * H + i] = (mask != 0) ? (float)mask : v;
    }
}

// ------------------------------------------------------------------- launch
extern "C" void kernel_launch(void* const* d_in, const int* in_sizes, int n_in,
                              void* d_out, int out_size)
{
    const int*   positions = nullptr;
    const float* hidden = nullptr;
    const float* w_qkv = nullptr;
    const float* w_o = nullptr;
    const float* gate_w = nullptr;
    const float* norms[3] = {nullptr, nullptr, nullptr};
    const float* big[3]   = {nullptr, nullptr, nullptr};
    int nn = 0, nb = 0;
    for (int i = 0; i < n_in; i++) {
        switch (in_sizes[i]) {
            case 2048:     positions = (const int*)d_in[i];   break;
            case 2097152:  hidden    = (const float*)d_in[i]; break;
            case 1572864:  w_qkv     = (const float*)d_in[i]; break;
            case 1048576:  w_o       = (const float*)d_in[i]; break;
            case 8192:     gate_w    = (const float*)d_in[i]; break;
            case 1024:     if (nn < 3) norms[nn++] = (const float*)d_in[i]; break;
            case 16777216: if (nb < 3) big[nb++]   = (const float*)d_in[i]; break;
            default: break;
        }
    }
    const float* norm_in   = norms[0];
    const float* norm_post = norms[1];
    const float* norm_next = norms[2];
    const float* w1 = big[0];
    const float* w2 = big[1];
    const float* w3 = big[2];
    float* out = (float*)d_out;

    // exact two-output size match only (elements, or bytes) — never OOB
    int write_x = (out_size == 2 * T * H || out_size == 2 * T * H * 4) ? 1 : 0;

    zero_cnt_kernel<<<1, 32>>>();
    rmsnorm_kernel<0><<<T, 256>>>(hidden, norm_in);
    gemm_kernel<0><<<dim3(QKVN / 64, T / 64), 256>>>(w_qkv, nullptr);
    rope_kernel<<<T, (NH + NKV) * 32>>>(positions);
    attn_kernel<<<dim3(T / 32, NH), 256>>>();
    gemm_kernel<1><<<dim3(H / 64, T / 64), 256>>>(w_o, hidden);
    rmsnorm_kernel<1><<<T, 256>>>(nullptr, norm_post);
    gate_kernel<<<T, 256>>>(gate_w);
    moe_gemm1<<<dim3(F / 64, T / 64, NE), 256>>>(w1, w3);
    moe_gemm2<<<dim3(H / 64, T / 64, NE), 256>>>(w2);
    selfcheck_kernel<<<1, 32>>>(hidden, w_qkv, w_o, w1, w2, w3);
    combine_kernel<<<T, 256>>>(norm_next, out, write_x);
}

// round 11
// speedup vs baseline: 1.1773x; 1.1773x over previous
#include <cuda_runtime.h>
#include <math.h>

constexpr int T   = 2048;
constexpr int H   = 1024;
constexpr int NH  = 16;
constexpr int NKV = 4;
constexpr int HD  = 64;
constexpr int NE  = 8;
constexpr int F   = 2048;
constexpr int QKVN = (NH + 2 * NKV) * HD;  // 1536
constexpr float EPS = 1e-5f;

using u64 = unsigned long long;

// ---- packed fp32x2 helpers (FFMA2 — only reachable via PTX) ---------------
__device__ __forceinline__ u64 dup2(float x) {
    u64 r; asm("mov.b64 %0, {%1, %1};" : "=l"(r) : "f"(x)); return r;
}
__device__ __forceinline__ u64 pack2(float x, float y) {
    u64 r; asm("mov.b64 %0, {%1, %2};" : "=l"(r) : "f"(x), "f"(y)); return r;
}
__device__ __forceinline__ void fma2(u64& d, u64 a, u64 b) {
    asm("fma.rn.f32x2 %0, %1, %2, %3;" : "=l"(d) : "l"(a), "l"(b), "l"(d));
}
__device__ __forceinline__ void mul2(u64& d, u64 a, u64 b) {
    asm("mul.rn.f32x2 %0, %1, %2;" : "=l"(d) : "l"(a), "l"(b));
}
__device__ __forceinline__ void unpack2(u64 v, float& x, float& y) {
    asm("mov.b64 {%0, %1}, %2;" : "=f"(x), "=f"(y) : "l"(v));
}

// ---- scratch: device globals, referenced ONLY inside device code ----------
__device__ float g_xnorm[T * H];
__device__ float g_qkv[T * QKVN];
__device__ float g_attn[T * NH * HD];
__device__ float g_x1[T * H];
__device__ float g_xnorm2[T * H];
__device__ int   g_cnt[NE];
__device__ int   g_ptok[NE * T];
__device__ int   g_slot[2 * T];
__device__ float g_gatew[2 * T];
__device__ float g_act[NE * T * F];
__device__ float g_y[NE * T * H];

// ---------------------------------------------------------------- utilities
__device__ __forceinline__ float block_sum_256(float v) {
    __shared__ float red[8];
    #pragma unroll
    for (int o = 16; o; o >>= 1) v += __shfl_xor_sync(0xffffffffu, v, o);
    if ((threadIdx.x & 31) == 0) red[threadIdx.x >> 5] = v;
    __syncthreads();
    if (threadIdx.x == 0) {
        float s = 0.f;
        #pragma unroll
        for (int i = 0; i < 8; i++) s += red[i];
        red[0] = s;
    }
    __syncthreads();
    float r = red[0];
    __syncthreads();
    return r;
}

// ------------------------------------------------------------------ kernels
__global__ void zero_cnt_kernel() {
    if (threadIdx.x < NE) g_cnt[threadIdx.x] = 0;
}

// MODE 0: x = xin(arg), out = g_xnorm ; MODE 1: x = g_x1, out = g_xnorm2
template <int MODE>
__global__ __launch_bounds__(256) void rmsnorm_kernel(
    const float* __restrict__ xin, const float* __restrict__ w)
{
    int t = blockIdx.x;
    const float* x = (MODE == 0) ? xin : (const float*)g_x1;
    float* out = (MODE == 0) ? g_xnorm : g_xnorm2;
    const float* xr = x + (size_t)t * H;
    float ss = 0.f;
    for (int i = threadIdx.x; i < H; i += 256) { float v = xr[i]; ss += v * v; }
    float tot = block_sum_256(ss);
    float scale = rsqrtf(tot / (float)H + EPS);
    for (int i = threadIdx.x; i < H; i += 256)
        out[(size_t)t * H + i] = xr[i] * scale * w[i];
}

// MODE 0: g_qkv = g_xnorm * B^T (N=QKVN). MODE 1: g_x1 = g_attn * B^T + resid (N=H)
template <int MODE>
__global__ __launch_bounds__(256) void gemm_kernel(
    const float* __restrict__ B, const float* __restrict__ resid)
{
    constexpr int K = H;
    constexpr int N = (MODE == 0) ? QKVN : H;
    const float* A = (MODE == 0) ? (const float*)g_xnorm : (const float*)g_attn;
    float* C = (MODE == 0) ? g_qkv : g_x1;

    __shared__ float As[64][16];
    __shared__ float Bs[16][64];
    int tid = threadIdx.x;
    int tx = tid & 15, ty = tid >> 4;
    int lrow = tid >> 2, lk4 = (tid & 3) << 2;
    int n0 = blockIdx.x * 64, m0 = blockIdx.y * 64;

    const float* Ap = A + (size_t)(m0 + lrow) * K + lk4;
    const float* Bp = B + (size_t)(n0 + lrow) * K + lk4;

    u64 acc2[4][2];
    #pragma unroll
    for (int i = 0; i < 4; i++) { acc2[i][0] = 0ull; acc2[i][1] = 0ull; }

    for (int k0 = 0; k0 < K; k0 += 16) {
        float4 av = *(const float4*)(Ap + k0);
        float4 bv = *(const float4*)(Bp + k0);
        *(float4*)&As[lrow][lk4] = av;
        Bs[lk4 + 0][lrow] = bv.x; Bs[lk4 + 1][lrow] = bv.y;
        Bs[lk4 + 2][lrow] = bv.z; Bs[lk4 + 3][lrow] = bv.w;
        __syncthreads();
        #pragma unroll
        for (int k = 0; k < 16; k++) {
            ulonglong2 bb = *(const ulonglong2*)&Bs[k][tx * 4];  // 16B aligned
            #pragma unroll
            for (int i = 0; i < 4; i++) {
                u64 ad = dup2(As[ty * 4 + i][k]);
                fma2(acc2[i][0], ad, bb.x);
                fma2(acc2[i][1], ad, bb.y);
            }
        }
        __syncthreads();
    }
    #pragma unroll
    for (int i = 0; i < 4; i++) {
        int m = m0 + ty * 4 + i;
        float c0, c1, c2, c3;
        unpack2(acc2[i][0], c0, c1);
        unpack2(acc2[i][1], c2, c3);
        float v4[4] = {c0, c1, c2, c3};
        #pragma unroll
        for (int j = 0; j < 4; j++) {
            int n = n0 + tx * 4 + j;
            float v = v4[j];
            if (MODE == 1) v += resid[(size_t)m * N + n];
            C[(size_t)m * N + n] = v;
        }
    }
}

__global__ void rope_kernel(const int* __restrict__ pos) {
    int t = blockIdx.x;
    int h = threadIdx.x >> 5, d = threadIdx.x & 31;
    float p = (float)pos[t];
    float inv = powf(10000.f, -(float)d / 32.f);
    float ang = p * inv;
    float c, s;
    sincosf(ang, &s, &c);
    float* base = g_qkv + (size_t)t * QKVN + h * HD;
    float x1 = base[d], x2 = base[d + 32];
    base[d]      = x1 * c - x2 * s;
    base[d + 32] = x2 * c + x1 * s;
}

__global__ __launch_bounds__(256) void attn_kernel() {
    __shared__ float Qs[32][65];
    __shared__ float KVs[64][65];
    __shared__ float Ps[32][65];
    int qt = blockIdx.x, h = blockIdx.y;
    int q0 = qt * 32;
    int kvh = h >> 2;
    int tid = threadIdx.x, tx = tid & 15, ty = tid >> 4;

    #pragma unroll
    for (int it = 0; it < 2; it++) {
        int idx = it * 256 + tid;
        int r = idx >> 4, dc = (idx & 15) << 2;
        float4 v = *(const float4*)(g_qkv + (size_t)(q0 + r) * QKVN + h * HD + dc);
        Qs[r][dc] = v.x; Qs[r][dc + 1] = v.y; Qs[r][dc + 2] = v.z; Qs[r][dc + 3] = v.w;
    }

    float m_i[2] = {-1e30f, -1e30f};
    float l_i[2] = {0.f, 0.f};
    u64 O2[2][2] = {{0ull, 0ull}, {0ull, 0ull}};
    int ktmax = qt >> 1;

    for (int kt = 0; kt <= ktmax; kt++) {
        int k0 = kt * 64;
        bool lastt = (kt == ktmax);
        __syncthreads();
        #pragma unroll
        for (int it = 0; it < 4; it++) {
            int idx = it * 256 + tid;
            int r = idx >> 4, dc = (idx & 15) << 2;
            float4 v = *(const float4*)(g_qkv + (size_t)(k0 + r) * QKVN + 1024 + kvh * HD + dc);
            KVs[r][dc] = v.x; KVs[r][dc + 1] = v.y; KVs[r][dc + 2] = v.z; KVs[r][dc + 3] = v.w;
        }
        __syncthreads();

        // S = Q K^T  (packed along j)
        u64 sv2[2][2] = {{0ull, 0ull}, {0ull, 0ull}};
        #pragma unroll 8
        for (int d = 0; d < 64; d++) {
            u64 kv01 = pack2(KVs[4 * tx + 0][d], KVs[4 * tx + 1][d]);
            u64 kv23 = pack2(KVs[4 * tx + 2][d], KVs[4 * tx + 3][d]);
            u64 q0d = dup2(Qs[2 * ty + 0][d]);
            u64 q1d = dup2(Qs[2 * ty + 1][d]);
            fma2(sv2[0][0], q0d, kv01); fma2(sv2[0][1], q0d, kv23);
            fma2(sv2[1][0], q1d, kv01); fma2(sv2[1][1], q1d, kv23);
        }
        float sv[2][4];
        unpack2(sv2[0][0], sv[0][0], sv[0][1]); unpack2(sv2[0][1], sv[0][2], sv[0][3]);
        unpack2(sv2[1][0], sv[1][0], sv[1][1]); unpack2(sv2[1][1], sv[1][2], sv[1][3]);

        #pragma unroll
        for (int i = 0; i < 2; i++) {
            int qrow = q0 + 2 * ty + i;
            float p[4], mx = -1e30f;
            #pragma unroll
            for (int j = 0; j < 4; j++) {
                float s = sv[i][j] * 0.125f;
                if (lastt && (k0 + 4 * tx + j > qrow)) s = -1e30f;
                p[j] = s;
                mx = fmaxf(mx, s);
            }
            #pragma unroll
            for (int o = 8; o; o >>= 1) mx = fmaxf(mx, __shfl_xor_sync(0xffffffffu, mx, o));
            float mnew = fmaxf(m_i[i], mx);
            float rs = 0.f;
            #pragma unroll
            for (int j = 0; j < 4; j++) { p[j] = __expf(p[j] - mnew); rs += p[j]; }
            #pragma unroll
            for (int o = 8; o; o >>= 1) rs += __shfl_xor_sync(0xffffffffu, rs, o);
            float fac = __expf(m_i[i] - mnew);
            l_i[i] = l_i[i] * fac + rs;
            m_i[i] = mnew;
            u64 facd = dup2(fac);
            mul2(O2[i][0], O2[i][0], facd);
            mul2(O2[i][1], O2[i][1], facd);
            #pragma unroll
            for (int j = 0; j < 4; j++) Ps[2 * ty + i][4 * tx + j] = p[j];
        }
        __syncthreads();
        #pragma unroll
        for (int it = 0; it < 4; it++) {
            int idx = it * 256 + tid;
            int r = idx >> 4, dc = (idx & 15) << 2;
            float4 v = *(const float4*)(g_qkv + (size_t)(k0 + r) * QKVN + 1280 + kvh * HD + dc);
            KVs[r][dc] = v.x; KVs[r][dc + 1] = v.y; KVs[r][dc + 2] = v.z; KVs[r][dc + 3] = v.w;
        }
        __syncthreads();
        // O += P V (packed along j; v pairs via scalar+pack, rows not 16B-aligned)
        #pragma unroll 8
        for (int k = 0; k < 64; k++) {
            u64 vv01 = pack2(KVs[k][4 * tx + 0], KVs[k][4 * tx + 1]);
            u64 vv23 = pack2(KVs[k][4 * tx + 2], KVs[k][4 * tx + 3]);
            u64 p0 = dup2(Ps[2 * ty + 0][k]);
            u64 p1 = dup2(Ps[2 * ty + 1][k]);
            fma2(O2[0][0], p0, vv01); fma2(O2[0][1], p0, vv23);
            fma2(O2[1][0], p1, vv01); fma2(O2[1][1], p1, vv23);
        }
    }
    #pragma unroll
    for (int i = 0; i < 2; i++) {
        float inv = 1.f / l_i[i];
        int qrow = q0 + 2 * ty + i;
        float o0, o1, o2, o3;
        unpack2(O2[i][0], o0, o1);
        unpack2(O2[i][1], o2, o3);
        float* dst = g_attn + (size_t)qrow * (NH * HD) + h * HD + 4 * tx;
        dst[0] = o0 * inv; dst[1] = o1 * inv; dst[2] = o2 * inv; dst[3] = o3 * inv;
    }
}

__global__ __launch_bounds__(256) void gate_kernel(const float* __restrict__ gate_w) {
    int t = blockIdx.x;
    const float* x = g_xnorm2 + (size_t)t * H;
    int w = threadIdx.x >> 5, lane = threadIdx.x & 31;
    float s = 0.f;
    const float* gw = gate_w + (size_t)w * H;
    for (int i = lane; i < H; i += 32) s += x[i] * gw[i];
    #pragma unroll
    for (int o = 16; o; o >>= 1) s += __shfl_xor_sync(0xffffffffu, s, o);
    __shared__ float logits[NE];
    if (lane == 0) logits[w] = s;
    __syncthreads();
    if (threadIdx.x == 0) {
        float mx = logits[0];
        #pragma unroll
        for (int e = 1; e < NE; e++) mx = fmaxf(mx, logits[e]);
        float p[NE];
        #pragma unroll
        for (int e = 0; e < NE; e++) p[e] = __expf(logits[e] - mx);
        int i1 = 0;
        #pragma unroll
        for (int e = 1; e < NE; e++) if (p[e] > p[i1]) i1 = e;
        int i2 = (i1 == 0) ? 1 : 0;
        #pragma unroll
        for (int e = 0; e < NE; e++) if (e != i1 && p[e] > p[i2]) i2 = e;
        float inv = 1.f / (p[i1] + p[i2]);
        int s0 = atomicAdd(&g_cnt[i1], 1);
        g_ptok[i1 * T + s0] = t;
        g_slot[2 * t + 0] = i1 * T + s0;
        g_gatew[2 * t + 0] = p[i1] * inv;
        int s1 = atomicAdd(&g_cnt[i2], 1);
        g_ptok[i2 * T + s1] = t;
        g_slot[2 * t + 1] = i2 * T + s1;
        g_gatew[2 * t + 1] = p[i2] * inv;
    }
}

__global__ __launch_bounds__(256) void moe_gemm1(
    const float* __restrict__ W1, const float* __restrict__ W3)
{
    int e = blockIdx.z;
    int cnt = g_cnt[e];
    int m0 = blockIdx.y * 64;
    if (m0 >= cnt) return;
    int n0 = blockIdx.x * 64;

    __shared__ float As[64][16];
    __shared__ float B1s[16][64];
    __shared__ float B3s[16][64];
    __shared__ int toks[64];

    int tid = threadIdx.x, tx = tid & 15, ty = tid >> 4;
    int lrow = tid >> 2, lk4 = (tid & 3) << 2;
    if (tid < 64) {
        int s = m0 + tid;
        toks[tid] = (s < cnt) ? g_ptok[e * T + s] : 0;
    }
    __syncthreads();

    const float* W1e = W1 + (size_t)e * F * H + (size_t)(n0 + lrow) * H + lk4;
    const float* W3e = W3 + (size_t)e * F * H + (size_t)(n0 + lrow) * H + lk4;
    const float* Ap = g_xnorm2 + (size_t)toks[lrow] * H + lk4;

    u64 acc1[4][2], acc3[4][2];
    #pragma unroll
    for (int i = 0; i < 4; i++) {
        acc1[i][0] = acc1[i][1] = 0ull;
        acc3[i][0] = acc3[i][1] = 0ull;
    }
    for (int k0 = 0; k0 < H; k0 += 16) {
        float4 av = *(const float4*)(Ap + k0);
        float4 b1 = *(const float4*)(W1e + k0);
        float4 b3 = *(const float4*)(W3e + k0);
        *(float4*)&As[lrow][lk4] = av;
        B1s[lk4 + 0][lrow] = b1.x; B1s[lk4 + 1][lrow] = b1.y;
        B1s[lk4 + 2][lrow] = b1.z; B1s[lk4 + 3][lrow] = b1.w;
        B3s[lk4 + 0][lrow] = b3.x; B3s[lk4 + 1][lrow] = b3.y;
        B3s[lk4 + 2][lrow] = b3.z; B3s[lk4 + 3][lrow] = b3.w;
        __syncthreads();
        #pragma unroll
        for (int k = 0; k < 16; k++) {
            ulonglong2 bb1 = *(const ulonglong2*)&B1s[k][tx * 4];
            ulonglong2 bb3 = *(const ulonglong2*)&B3s[k][tx * 4];
            #pragma unroll
            for (int i = 0; i < 4; i++) {
                u64 ad = dup2(As[ty * 4 + i][k]);
                fma2(acc1[i][0], ad, bb1.x);
                fma2(acc1[i][1], ad, bb1.y);
                fma2(acc3[i][0], ad, bb3.x);
                fma2(acc3[i][1], ad, bb3.y);
            }
        }
        __syncthreads();
    }
    #pragma unroll
    for (int i = 0; i < 4; i++) {
        int s = m0 + ty * 4 + i;
        if (s >= cnt) continue;
        float a0, a1v, a2, a3v, c0, c1, c2, c3;
        unpack2(acc1[i][0], a0, a1v); unpack2(acc1[i][1], a2, a3v);
        unpack2(acc3[i][0], c0, c1);  unpack2(acc3[i][1], c2, c3);
        float h1v[4] = {a0, a1v, a2, a3v};
        float h3v[4] = {c0, c1, c2, c3};
        float* dst = g_act + (size_t)(e * T + s) * F + n0 + tx * 4;
        #pragma unroll
        for (int j = 0; j < 4; j++) {
            float h1 = h1v[j];
            float sig = 1.f / (1.f + __expf(-h1));
            dst[j] = h1 * sig * h3v[j];
        }
    }
}

__global__ __launch_bounds__(256) void moe_gemm2(const float* __restrict__ W2) {
    int e = blockIdx.z;
    int cnt = g_cnt[e];
    int m0 = blockIdx.y * 64;
    if (m0 >= cnt) return;
    int n0 = blockIdx.x * 64;

    __shared__ float As[64][16];
    __shared__ float Bs[16][64];
    int tid = threadIdx.x, tx = tid & 15, ty = tid >> 4;
    int lrow = tid >> 2, lk4 = (tid & 3) << 2;

    const float* Ap = g_act + (size_t)(e * T + m0 + lrow) * F + lk4;
    const float* Bp = W2 + (size_t)e * H * F + (size_t)(n0 + lrow) * F + lk4;

    u64 acc2[4][2];
    #pragma unroll
    for (int i = 0; i < 4; i++) { acc2[i][0] = 0ull; acc2[i][1] = 0ull; }

    for (int k0 = 0; k0 < F; k0 += 16) {
        float4 av = *(const float4*)(Ap + k0);
        float4 bv = *(const float4*)(Bp + k0);
        *(float4*)&As[lrow][lk4] = av;
        Bs[lk4 + 0][lrow] = bv.x; Bs[lk4 + 1][lrow] = bv.y;
        Bs[lk4 + 2][lrow] = bv.z; Bs[lk4 + 3][lrow] = bv.w;
        __syncthreads();
        #pragma unroll
        for (int k = 0; k < 16; k++) {
            ulonglong2 bb = *(const ulonglong2*)&Bs[k][tx * 4];
            #pragma unroll
            for (int i = 0; i < 4; i++) {
                u64 ad = dup2(As[ty * 4 + i][k]);
                fma2(acc2[i][0], ad, bb.x);
                fma2(acc2[i][1], ad, bb.y);
            }
        }
        __syncthreads();
    }
    #pragma unroll
    for (int i = 0; i < 4; i++) {
        int s = m0 + ty * 4 + i;
        if (s >= cnt) continue;
        float c0, c1, c2, c3;
        unpack2(acc2[i][0], c0, c1);
        unpack2(acc2[i][1], c2, c3);
        float* dst = g_y + (size_t)(e * T + s) * H + n0 + tx * 4;
        dst[0] = c0; dst[1] = c1; dst[2] = c2; dst[3] = c3;
    }
}

// x = x1 + g0*y0 + g1*y1; rmsnorm(x) -> out[0..T*H); x -> out[T*H..) if room.
__global__ __launch_bounds__(256) void combine_kernel(
    const float* __restrict__ w_next, float* __restrict__ out, int write_x)
{
    __shared__ float xs[H];
    int t = blockIdx.x;
    int s0 = g_slot[2 * t + 0], s1 = g_slot[2 * t + 1];
    float g0 = g_gatew[2 * t + 0], g1 = g_gatew[2 * t + 1];
    float ss = 0.f;
    for (int i = threadIdx.x; i < H; i += 256) {
        float v = g_x1[(size_t)t * H + i]
                + g0 * g_y[(size_t)s0 * H + i]
                + g1 * g_y[(size_t)s1 * H + i];
        xs[i] = v;
        if (write_x) out[(size_t)T * H + (size_t)t * H + i] = v;
        ss += v * v;
    }
    float tot = block_sum_256(ss);
    float scale = rsqrtf(tot / (float)H + EPS);
    __syncthreads();
    for (int i = threadIdx.x; i < H; i += 256)
        out[(size_t)t * H + i] = xs[i] * scale * w_next[i];
}

// ------------------------------------------------------------------- launch
extern "C" void kernel_launch(void* const* d_in, const int* in_sizes, int n_in,
                              void* d_out, int out_size)
{
    const int*   positions = nullptr;
    const float* hidden = nullptr;
    const float* w_qkv = nullptr;
    const float* w_o = nullptr;
    const float* gate_w = nullptr;
    const float* norms[3] = {nullptr, nullptr, nullptr};
    const float* big[3]   = {nullptr, nullptr, nullptr};
    int nn = 0, nb = 0;
    for (int i = 0; i < n_in; i++) {
        switch (in_sizes[i]) {
            case 2048:     positions = (const int*)d_in[i];   break;
            case 2097152:  hidden    = (const float*)d_in[i]; break;
            case 1572864:  w_qkv     = (const float*)d_in[i]; break;
            case 1048576:  w_o       = (const float*)d_in[i]; break;
            case 8192:     gate_w    = (const float*)d_in[i]; break;
            case 1024:     if (nn < 3) norms[nn++] = (const float*)d_in[i]; break;
            case 16777216: if (nb < 3) big[nb++]   = (const float*)d_in[i]; break;
            default: break;
        }
    }
    const float* norm_in   = norms[0];
    const float* norm_post = norms[1];
    const float* norm_next = norms[2];
    const float* w1 = big[0];
    const float* w2 = big[1];
    const float* w3 = big[2];
    float* out = (float*)d_out;

    int write_x = (out_size == 2 * T * H || out_size == 2 * T * H * 4) ? 1 : 0;

    zero_cnt_kernel<<<1, 32>>>();
    rmsnorm_kernel<0><<<T, 256>>>(hidden, norm_in);
    gemm_kernel<0><<<dim3(QKVN / 64, T / 64), 256>>>(w_qkv, nullptr);
    rope_kernel<<<T, (NH + NKV) * 32>>>(positions);
    attn_kernel<<<dim3(T / 32, NH), 256>>>();
    gemm_kernel<1><<<dim3(H / 64, T / 64), 256>>>(w_o, hidden);
    rmsnorm_kernel<1><<<T, 256>>>(nullptr, norm_post);
    gate_kernel<<<T, 256>>>(gate_w);
    moe_gemm1<<<dim3(F / 64, T / 64, NE), 256>>>(w1, w3);
    moe_gemm2<<<dim3(H / 64, T / 64, NE), 256>>>(w2);
    combine_kernel<<<T, 256>>>(norm_next, out, write_x);
}

// round 12
// speedup vs baseline: 1.2214x; 1.0374x over previous
#include <cuda_runtime.h>
#include <math.h>

constexpr int T   = 2048;
constexpr int H   = 1024;
constexpr int NH  = 16;
constexpr int NKV = 4;
constexpr int HD  = 64;
constexpr int NE  = 8;
constexpr int F   = 2048;
constexpr int QKVN = (NH + 2 * NKV) * HD;  // 1536
constexpr float EPS = 1e-5f;

using u64 = unsigned long long;

// ---- packed fp32x2 helpers (FFMA2 — only reachable via PTX) ---------------
__device__ __forceinline__ u64 dup2(float x) {
    u64 r; asm("mov.b64 %0, {%1, %1};" : "=l"(r) : "f"(x)); return r;
}
__device__ __forceinline__ u64 pack2(float x, float y) {
    u64 r; asm("mov.b64 %0, {%1, %2};" : "=l"(r) : "f"(x), "f"(y)); return r;
}
__device__ __forceinline__ void fma2(u64& d, u64 a, u64 b) {
    asm("fma.rn.f32x2 %0, %1, %2, %3;" : "=l"(d) : "l"(a), "l"(b), "l"(d));
}
__device__ __forceinline__ void mul2(u64& d, u64 a, u64 b) {
    asm("mul.rn.f32x2 %0, %1, %2;" : "=l"(d) : "l"(a), "l"(b));
}
__device__ __forceinline__ void unpack2(u64 v, float& x, float& y) {
    asm("mov.b64 {%0, %1}, %2;" : "=f"(x), "=f"(y) : "l"(v));
}

// ---- scratch: device globals, referenced ONLY inside device code ----------
__device__ float g_xnorm[T * H];
__device__ float g_qkv[T * QKVN];
__device__ float g_attn[T * NH * HD];
__device__ float g_x1[T * H];
__device__ float g_xnorm2[T * H];
__device__ int   g_cnt[NE];
__device__ int   g_ptok[NE * T];
__device__ int   g_slot[2 * T];
__device__ float g_gatew[2 * T];
__device__ float g_act[NE * T * F];
__device__ float g_y[NE * T * H];

// ---------------------------------------------------------------- utilities
__device__ __forceinline__ float block_sum_256(float v) {
    __shared__ float red[8];
    #pragma unroll
    for (int o = 16; o; o >>= 1) v += __shfl_xor_sync(0xffffffffu, v, o);
    if ((threadIdx.x & 31) == 0) red[threadIdx.x >> 5] = v;
    __syncthreads();
    if (threadIdx.x == 0) {
        float s = 0.f;
        #pragma unroll
        for (int i = 0; i < 8; i++) s += red[i];
        red[0] = s;
    }
    __syncthreads();
    float r = red[0];
    __syncthreads();
    return r;
}

// ------------------------------------------------------------------ kernels
__global__ void zero_cnt_kernel() {
    if (threadIdx.x < NE) g_cnt[threadIdx.x] = 0;
}

template <int MODE>
__global__ __launch_bounds__(256) void rmsnorm_kernel(
    const float* __restrict__ xin, const float* __restrict__ w)
{
    int t = blockIdx.x;
    const float* x = (MODE == 0) ? xin : (const float*)g_x1;
    float* out = (MODE == 0) ? g_xnorm : g_xnorm2;
    const float* xr = x + (size_t)t * H;
    float ss = 0.f;
    for (int i = threadIdx.x; i < H; i += 256) { float v = xr[i]; ss += v * v; }
    float tot = block_sum_256(ss);
    float scale = rsqrtf(tot / (float)H + EPS);
    for (int i = threadIdx.x; i < H; i += 256)
        out[(size_t)t * H + i] = xr[i] * scale * w[i];
}

// ------------- unified 128x128 GEMM, 8x8 per thread, FFMA2 inner ----------
// MODE 0: g_qkv  = g_xnorm * w_qkv^T                (N=QKVN, K=H)
// MODE 1: g_x1   = g_attn  * w_o^T + resid          (N=H,    K=H)
// MODE 2: g_act  = Xg      * w3^T   (gathered rows) (N=F,    K=H)
// MODE 3: g_act  = silu(Xg * w1^T) * g_act          (N=F,    K=H)
// MODE 4: g_y    = g_act   * w2^T                   (N=H,    K=F)
template <int MODE>
__global__ __launch_bounds__(256) void gemm128(
    const float* __restrict__ B, const float* __restrict__ resid)
{
    constexpr int K = (MODE == 4) ? F : H;
    constexpr int N = (MODE == 0) ? QKVN : ((MODE == 2 || MODE == 3) ? F : H);

    int e   = (MODE >= 2) ? blockIdx.z : 0;
    int cnt = (MODE >= 2) ? g_cnt[e] : T;
    int m0  = blockIdx.y * 128;
    if (m0 >= cnt) return;
    int n0  = blockIdx.x * 128;

    __shared__ float As[16][128];
    __shared__ float Bs[16][128];
    __shared__ int   toks[128];

    int tid = threadIdx.x;
    int tx = tid & 15, ty = tid >> 4;
    int lr = tid >> 1;            // 0..127 : row loaded by this thread
    int lk = (tid & 1) * 8;       // 0 or 8 : k-offset within 16-wide slab

    if (MODE == 2 || MODE == 3) {
        if (tid < 128) {
            int s = m0 + tid;
            toks[tid] = (s < cnt) ? g_ptok[e * T + s] : g_ptok[e * T];
        }
        __syncthreads();
    }

    const float* Arow;
    if (MODE == 0)      Arow = g_xnorm + (size_t)(m0 + lr) * H;
    else if (MODE == 1) Arow = g_attn  + (size_t)(m0 + lr) * H;
    else if (MODE == 4) Arow = g_act   + (size_t)(e * T + m0 + lr) * F;
    else                Arow = g_xnorm2 + (size_t)toks[lr] * H;

    size_t estride = (MODE == 2 || MODE == 3) ? (size_t)F * H
                   : (MODE == 4) ? (size_t)H * F : 0;
    const float* Brow = B + (size_t)e * estride + (size_t)(n0 + lr) * K;

    u64 acc[8][4];
    #pragma unroll
    for (int i = 0; i < 8; i++)
        #pragma unroll
        for (int j = 0; j < 4; j++) acc[i][j] = 0ull;

    for (int k0 = 0; k0 < K; k0 += 16) {
        float4 a0 = *(const float4*)(Arow + k0 + lk);
        float4 a1 = *(const float4*)(Arow + k0 + lk + 4);
        float4 b0 = *(const float4*)(Brow + k0 + lk);
        float4 b1 = *(const float4*)(Brow + k0 + lk + 4);
        As[lk + 0][lr] = a0.x; As[lk + 1][lr] = a0.y; As[lk + 2][lr] = a0.z; As[lk + 3][lr] = a0.w;
        As[lk + 4][lr] = a1.x; As[lk + 5][lr] = a1.y; As[lk + 6][lr] = a1.z; As[lk + 7][lr] = a1.w;
        Bs[lk + 0][lr] = b0.x; Bs[lk + 1][lr] = b0.y; Bs[lk + 2][lr] = b0.z; Bs[lk + 3][lr] = b0.w;
        Bs[lk + 4][lr] = b1.x; Bs[lk + 5][lr] = b1.y; Bs[lk + 6][lr] = b1.z; Bs[lk + 7][lr] = b1.w;
        __syncthreads();
        #pragma unroll
        for (int k = 0; k < 16; k++) {
            float4 af0 = *(const float4*)&As[k][ty * 8];
            float4 af1 = *(const float4*)&As[k][ty * 8 + 4];
            ulonglong2 bb0 = *(const ulonglong2*)&Bs[k][tx * 8];
            ulonglong2 bb1 = *(const ulonglong2*)&Bs[k][tx * 8 + 4];
            float am[8] = {af0.x, af0.y, af0.z, af0.w, af1.x, af1.y, af1.z, af1.w};
            #pragma unroll
            for (int i = 0; i < 8; i++) {
                u64 ad = dup2(am[i]);
                fma2(acc[i][0], ad, bb0.x);
                fma2(acc[i][1], ad, bb0.y);
                fma2(acc[i][2], ad, bb1.x);
                fma2(acc[i][3], ad, bb1.y);
            }
        }
        __syncthreads();
    }

    #pragma unroll
    for (int i = 0; i < 8; i++) {
        int m = m0 + ty * 8 + i;
        if ((MODE >= 2) && m >= cnt) continue;
        float c[8];
        unpack2(acc[i][0], c[0], c[1]);
        unpack2(acc[i][1], c[2], c[3]);
        unpack2(acc[i][2], c[4], c[5]);
        unpack2(acc[i][3], c[6], c[7]);
        int n = n0 + tx * 8;
        if (MODE == 0) {
            float* dst = g_qkv + (size_t)m * QKVN + n;
            *(float4*)dst       = make_float4(c[0], c[1], c[2], c[3]);
            *(float4*)(dst + 4) = make_float4(c[4], c[5], c[6], c[7]);
        } else if (MODE == 1) {
            float* dst = g_x1 + (size_t)m * H + n;
            const float* r = resid + (size_t)m * H + n;
            float4 r0 = *(const float4*)r, r1 = *(const float4*)(r + 4);
            *(float4*)dst       = make_float4(c[0] + r0.x, c[1] + r0.y, c[2] + r0.z, c[3] + r0.w);
            *(float4*)(dst + 4) = make_float4(c[4] + r1.x, c[5] + r1.y, c[6] + r1.z, c[7] + r1.w);
        } else if (MODE == 2) {
            float* dst = g_act + (size_t)(e * T + m) * F + n;
            *(float4*)dst       = make_float4(c[0], c[1], c[2], c[3]);
            *(float4*)(dst + 4) = make_float4(c[4], c[5], c[6], c[7]);
        } else if (MODE == 3) {
            float* dst = g_act + (size_t)(e * T + m) * F + n;
            float4 h30 = *(const float4*)dst, h31 = *(const float4*)(dst + 4);
            float h3[8] = {h30.x, h30.y, h30.z, h30.w, h31.x, h31.y, h31.z, h31.w};
            float o[8];
            #pragma unroll
            for (int j = 0; j < 8; j++) {
                float h1 = c[j];
                float sig = 1.f / (1.f + __expf(-h1));
                o[j] = h1 * sig * h3[j];
            }
            *(float4*)dst       = make_float4(o[0], o[1], o[2], o[3]);
            *(float4*)(dst + 4) = make_float4(o[4], o[5], o[6], o[7]);
        } else {
            float* dst = g_y + (size_t)(e * T + m) * H + n;
            *(float4*)dst       = make_float4(c[0], c[1], c[2], c[3]);
            *(float4*)(dst + 4) = make_float4(c[4], c[5], c[6], c[7]);
        }
    }
}

__global__ void rope_kernel(const int* __restrict__ pos) {
    int t = blockIdx.x;
    int h = threadIdx.x >> 5, d = threadIdx.x & 31;
    float p = (float)pos[t];
    float inv = powf(10000.f, -(float)d / 32.f);
    float ang = p * inv;
    float c, s;
    sincosf(ang, &s, &c);
    float* base = g_qkv + (size_t)t * QKVN + h * HD;
    float x1 = base[d], x2 = base[d + 32];
    base[d]      = x1 * c - x2 * s;
    base[d + 32] = x2 * c + x1 * s;
}

__global__ __launch_bounds__(256) void attn_kernel() {
    __shared__ float Qs[32][65];
    __shared__ float KVs[64][65];
    __shared__ float Ps[32][65];
    int qt = blockIdx.x, h = blockIdx.y;
    int q0 = qt * 32;
    int kvh = h >> 2;
    int tid = threadIdx.x, tx = tid & 15, ty = tid >> 4;

    #pragma unroll
    for (int it = 0; it < 2; it++) {
        int idx = it * 256 + tid;
        int r = idx >> 4, dc = (idx & 15) << 2;
        float4 v = *(const float4*)(g_qkv + (size_t)(q0 + r) * QKVN + h * HD + dc);
        Qs[r][dc] = v.x; Qs[r][dc + 1] = v.y; Qs[r][dc + 2] = v.z; Qs[r][dc + 3] = v.w;
    }

    float m_i[2] = {-1e30f, -1e30f};
    float l_i[2] = {0.f, 0.f};
    u64 O2[2][2] = {{0ull, 0ull}, {0ull, 0ull}};
    int ktmax = qt >> 1;

    for (int kt = 0; kt <= ktmax; kt++) {
        int k0 = kt * 64;
        bool lastt = (kt == ktmax);
        __syncthreads();
        #pragma unroll
        for (int it = 0; it < 4; it++) {
            int idx = it * 256 + tid;
            int r = idx >> 4, dc = (idx & 15) << 2;
            float4 v = *(const float4*)(g_qkv + (size_t)(k0 + r) * QKVN + 1024 + kvh * HD + dc);
            KVs[r][dc] = v.x; KVs[r][dc + 1] = v.y; KVs[r][dc + 2] = v.z; KVs[r][dc + 3] = v.w;
        }
        __syncthreads();

        u64 sv2[2][2] = {{0ull, 0ull}, {0ull, 0ull}};
        #pragma unroll 8
        for (int d = 0; d < 64; d++) {
            u64 kv01 = pack2(KVs[4 * tx + 0][d], KVs[4 * tx + 1][d]);
            u64 kv23 = pack2(KVs[4 * tx + 2][d], KVs[4 * tx + 3][d]);
            u64 q0d = dup2(Qs[2 * ty + 0][d]);
            u64 q1d = dup2(Qs[2 * ty + 1][d]);
            fma2(sv2[0][0], q0d, kv01); fma2(sv2[0][1], q0d, kv23);
            fma2(sv2[1][0], q1d, kv01); fma2(sv2[1][1], q1d, kv23);
        }
        float sv[2][4];
        unpack2(sv2[0][0], sv[0][0], sv[0][1]); unpack2(sv2[0][1], sv[0][2], sv[0][3]);
        unpack2(sv2[1][0], sv[1][0], sv[1][1]); unpack2(sv2[1][1], sv[1][2], sv[1][3]);

        #pragma unroll
        for (int i = 0; i < 2; i++) {
            int qrow = q0 + 2 * ty + i;
            float p[4], mx = -1e30f;
            #pragma unroll
            for (int j = 0; j < 4; j++) {
                float s = sv[i][j] * 0.125f;
                if (lastt && (k0 + 4 * tx + j > qrow)) s = -1e30f;
                p[j] = s;
                mx = fmaxf(mx, s);
            }
            #pragma unroll
            for (int o = 8; o; o >>= 1) mx = fmaxf(mx, __shfl_xor_sync(0xffffffffu, mx, o));
            float mnew = fmaxf(m_i[i], mx);
            float rs = 0.f;
            #pragma unroll
            for (int j = 0; j < 4; j++) { p[j] = __expf(p[j] - mnew); rs += p[j]; }
            #pragma unroll
            for (int o = 8; o; o >>= 1) rs += __shfl_xor_sync(0xffffffffu, rs, o);
            float fac = __expf(m_i[i] - mnew);
            l_i[i] = l_i[i] * fac + rs;
            m_i[i] = mnew;
            u64 facd = dup2(fac);
            mul2(O2[i][0], O2[i][0], facd);
            mul2(O2[i][1], O2[i][1], facd);
            #pragma unroll
            for (int j = 0; j < 4; j++) Ps[2 * ty + i][4 * tx + j] = p[j];
        }
        __syncthreads();
        #pragma unroll
        for (int it = 0; it < 4; it++) {
            int idx = it * 256 + tid;
            int r = idx >> 4, dc = (idx & 15) << 2;
            float4 v = *(const float4*)(g_qkv + (size_t)(k0 + r) * QKVN + 1280 + kvh * HD + dc);
            KVs[r][dc] = v.x; KVs[r][dc + 1] = v.y; KVs[r][dc + 2] = v.z; KVs[r][dc + 3] = v.w;
        }
        __syncthreads();
        #pragma unroll 8
        for (int k = 0; k < 64; k++) {
            u64 vv01 = pack2(KVs[k][4 * tx + 0], KVs[k][4 * tx + 1]);
            u64 vv23 = pack2(KVs[k][4 * tx + 2], KVs[k][4 * tx + 3]);
            u64 p0 = dup2(Ps[2 * ty + 0][k]);
            u64 p1 = dup2(Ps[2 * ty + 1][k]);
            fma2(O2[0][0], p0, vv01); fma2(O2[0][1], p0, vv23);
            fma2(O2[1][0], p1, vv01); fma2(O2[1][1], p1, vv23);
        }
    }
    #pragma unroll
    for (int i = 0; i < 2; i++) {
        float inv = 1.f / l_i[i];
        int qrow = q0 + 2 * ty + i;
        float o0, o1, o2, o3;
        unpack2(O2[i][0], o0, o1);
        unpack2(O2[i][1], o2, o3);
        float* dst = g_attn + (size_t)qrow * (NH * HD) + h * HD + 4 * tx;
        dst[0] = o0 * inv; dst[1] = o1 * inv; dst[2] = o2 * inv; dst[3] = o3 * inv;
    }
}

__global__ __launch_bounds__(256) void gate_kernel(const float* __restrict__ gate_w) {
    int t = blockIdx.x;
    const float* x = g_xnorm2 + (size_t)t * H;
    int w = threadIdx.x >> 5, lane = threadIdx.x & 31;
    float s = 0.f;
    const float* gw = gate_w + (size_t)w * H;
    for (int i = lane; i < H; i += 32) s += x[i] * gw[i];
    #pragma unroll
    for (int o = 16; o; o >>= 1) s += __shfl_xor_sync(0xffffffffu, s, o);
    __shared__ float logits[NE];
    if (lane == 0) logits[w] = s;
    __syncthreads();
    if (threadIdx.x == 0) {
        float mx = logits[0];
        #pragma unroll
        for (int e = 1; e < NE; e++) mx = fmaxf(mx, logits[e]);
        float p[NE];
        #pragma unroll
        for (int e = 0; e < NE; e++) p[e] = __expf(logits[e] - mx);
        int i1 = 0;
        #pragma unroll
        for (int e = 1; e < NE; e++) if (p[e] > p[i1]) i1 = e;
        int i2 = (i1 == 0) ? 1 : 0;
        #pragma unroll
        for (int e = 0; e < NE; e++) if (e != i1 && p[e] > p[i2]) i2 = e;
        float inv = 1.f / (p[i1] + p[i2]);
        int s0 = atomicAdd(&g_cnt[i1], 1);
        g_ptok[i1 * T + s0] = t;
        g_slot[2 * t + 0] = i1 * T + s0;
        g_gatew[2 * t + 0] = p[i1] * inv;
        int s1 = atomicAdd(&g_cnt[i2], 1);
        g_ptok[i2 * T + s1] = t;
        g_slot[2 * t + 1] = i2 * T + s1;
        g_gatew[2 * t + 1] = p[i2] * inv;
    }
}

// x = x1 + g0*y0 + g1*y1; rmsnorm(x) -> out[0..T*H); x -> out[T*H..) if room.
__global__ __launch_bounds__(256) void combine_kernel(
    const float* __restrict__ w_next, float* __restrict__ out, int write_x)
{
    __shared__ float xs[H];
    int t = blockIdx.x;
    int s0 = g_slot[2 * t + 0], s1 = g_slot[2 * t + 1];
    float g0 = g_gatew[2 * t + 0], g1 = g_gatew[2 * t + 1];
    float ss = 0.f;
    for (int i = threadIdx.x; i < H; i += 256) {
        float v = g_x1[(size_t)t * H + i]
                + g0 * g_y[(size_t)s0 * H + i]
                + g1 * g_y[(size_t)s1 * H + i];
        xs[i] = v;
        if (write_x) out[(size_t)T * H + (size_t)t * H + i] = v;
        ss += v * v;
    }
    float tot = block_sum_256(ss);
    float scale = rsqrtf(tot / (float)H + EPS);
    __syncthreads();
    for (int i = threadIdx.x; i < H; i += 256)
        out[(size_t)t * H + i] = xs[i] * scale * w_next[i];
}

// ------------------------------------------------------------------- launch
extern "C" void kernel_launch(void* const* d_in, const int* in_sizes, int n_in,
                              void* d_out, int out_size)
{
    const int*   positions = nullptr;
    const float* hidden = nullptr;
    const float* w_qkv = nullptr;
    const float* w_o = nullptr;
    const float* gate_w = nullptr;
    const float* norms[3] = {nullptr, nullptr, nullptr};
    const float* big[3]   = {nullptr, nullptr, nullptr};
    int nn = 0, nb = 0;
    for (int i = 0; i < n_in; i++) {
        switch (in_sizes[i]) {
            case 2048:     positions = (const int*)d_in[i];   break;
            case 2097152:  hidden    = (const float*)d_in[i]; break;
            case 1572864:  w_qkv     = (const float*)d_in[i]; break;
            case 1048576:  w_o       = (const float*)d_in[i]; break;
            case 8192:     gate_w    = (const float*)d_in[i]; break;
            case 1024:     if (nn < 3) norms[nn++] = (const float*)d_in[i]; break;
            case 16777216: if (nb < 3) big[nb++]   = (const float*)d_in[i]; break;
            default: break;
        }
    }
    const float* norm_in   = norms[0];
    const float* norm_post = norms[1];
    const float* norm_next = norms[2];
    const float* w1 = big[0];
    const float* w2 = big[1];
    const float* w3 = big[2];
    float* out = (float*)d_out;

    int write_x = (out_size == 2 * T * H || out_size == 2 * T * H * 4) ? 1 : 0;

    zero_cnt_kernel<<<1, 32>>>();
    rmsnorm_kernel<0><<<T, 256>>>(hidden, norm_in);
    gemm128<0><<<dim3(QKVN / 128, T / 128), 256>>>(w_qkv, nullptr);
    rope_kernel<<<T, (NH + NKV) * 32>>>(positions);
    attn_kernel<<<dim3(T / 32, NH), 256>>>();
    gemm128<1><<<dim3(H / 128, T / 128), 256>>>(w_o, hidden);
    rmsnorm_kernel<1><<<T, 256>>>(nullptr, norm_post);
    gate_kernel<<<T, 256>>>(gate_w);
    gemm128<2><<<dim3(F / 128, T / 128, NE), 256>>>(w3, nullptr);
    gemm128<3><<<dim3(F / 128, T / 128, NE), 256>>>(w1, nullptr);
    gemm128<4><<<dim3(H / 128, T / 128, NE), 256>>>(w2, nullptr);
    combine_kernel<<<T, 256>>>(norm_next, out, write_x);
}

// round 13
// speedup vs baseline: 1.9190x; 1.5712x over previous
#include <cuda_runtime.h>
#include <math.h>

constexpr int T   = 2048;
constexpr int H   = 1024;
constexpr int NH  = 16;
constexpr int NKV = 4;
constexpr int HD  = 64;
constexpr int NE  = 8;
constexpr int F   = 2048;
constexpr int QKVN = (NH + 2 * NKV) * HD;  // 1536
constexpr float EPS = 1e-5f;

using u64 = unsigned long long;

// ---- packed fp32x2 helpers (attention only) -------------------------------
__device__ __forceinline__ u64 dup2(float x) {
    u64 r; asm("mov.b64 %0, {%1, %1};" : "=l"(r) : "f"(x)); return r;
}
__device__ __forceinline__ u64 pack2(float x, float y) {
    u64 r; asm("mov.b64 %0, {%1, %2};" : "=l"(r) : "f"(x), "f"(y)); return r;
}
__device__ __forceinline__ void fma2(u64& d, u64 a, u64 b) {
    asm("fma.rn.f32x2 %0, %1, %2, %3;" : "=l"(d) : "l"(a), "l"(b), "l"(d));
}
__device__ __forceinline__ void mul2(u64& d, u64 a, u64 b) {
    asm("mul.rn.f32x2 %0, %1, %2;" : "=l"(d) : "l"(a), "l"(b));
}
__device__ __forceinline__ void unpack2(u64 v, float& x, float& y) {
    asm("mov.b64 {%0, %1}, %2;" : "=f"(x), "=f"(y) : "l"(v));
}

// ---- tf32 tensor-core helpers ---------------------------------------------
__device__ __forceinline__ unsigned f2tf(float x) {
    unsigned r; asm("cvt.rna.tf32.f32 %0, %1;" : "=r"(r) : "f"(x)); return r;
}
__device__ __forceinline__ void mma_tf32(float* c, const unsigned* a, const unsigned* b) {
    asm("mma.sync.aligned.m16n8k8.row.col.f32.tf32.tf32.f32 "
        "{%0,%1,%2,%3}, {%4,%5,%6,%7}, {%8,%9}, {%0,%1,%2,%3};"
        : "+f"(c[0]), "+f"(c[1]), "+f"(c[2]), "+f"(c[3])
        : "r"(a[0]), "r"(a[1]), "r"(a[2]), "r"(a[3]), "r"(b[0]), "r"(b[1]));
}

// ---- scratch: device globals, referenced ONLY inside device code ----------
__device__ float g_xnorm[T * H];
__device__ float g_qkv[T * QKVN];
__device__ float g_attn[T * NH * HD];
__device__ float g_x1[T * H];
__device__ float g_xnorm2[T * H];
__device__ int   g_cnt[NE];
__device__ int   g_ptok[NE * T];
__device__ int   g_slot[2 * T];
__device__ float g_gatew[2 * T];
__device__ float g_act[NE * T * F];
__device__ float g_y[NE * T * H];

// ---------------------------------------------------------------- utilities
__device__ __forceinline__ float block_sum_256(float v) {
    __shared__ float red[8];
    #pragma unroll
    for (int o = 16; o; o >>= 1) v += __shfl_xor_sync(0xffffffffu, v, o);
    if ((threadIdx.x & 31) == 0) red[threadIdx.x >> 5] = v;
    __syncthreads();
    if (threadIdx.x == 0) {
        float s = 0.f;
        #pragma unroll
        for (int i = 0; i < 8; i++) s += red[i];
        red[0] = s;
    }
    __syncthreads();
    float r = red[0];
    __syncthreads();
    return r;
}

// ------------------------------------------------------------------ kernels
__global__ void zero_cnt_kernel() {
    if (threadIdx.x < NE) g_cnt[threadIdx.x] = 0;
}

template <int MODE>
__global__ __launch_bounds__(256) void rmsnorm_kernel(
    const float* __restrict__ xin, const float* __restrict__ w)
{
    int t = blockIdx.x;
    const float* x = (MODE == 0) ? xin : (const float*)g_x1;
    float* out = (MODE == 0) ? g_xnorm : g_xnorm2;
    const float* xr = x + (size_t)t * H;
    float ss = 0.f;
    for (int i = threadIdx.x; i < H; i += 256) { float v = xr[i]; ss += v * v; }
    float tot = block_sum_256(ss);
    float scale = rsqrtf(tot / (float)H + EPS);
    for (int i = threadIdx.x; i < H; i += 256)
        out[(size_t)t * H + i] = xr[i] * scale * w[i];
}

// ---------------- unified 128x128 TF32 tensor-core GEMM --------------------
// MODE 0: g_qkv  = g_xnorm * w_qkv^T                (N=QKVN, K=H)
// MODE 1: g_x1   = g_attn  * w_o^T + resid          (N=H,    K=H)
// MODE 2: g_act  = Xg      * w3^T   (gathered rows) (N=F,    K=H)
// MODE 3: g_act  = silu(Xg * w1^T) * g_act          (N=F,    K=H)
// MODE 4: g_y    = g_act   * w2^T                   (N=H,    K=F)
template <int MODE>
__global__ __launch_bounds__(256) void gemm_tc(
    const float* __restrict__ B, const float* __restrict__ resid)
{
    constexpr int K = (MODE == 4) ? F : H;

    int e   = (MODE >= 2) ? blockIdx.z : 0;
    int cnt = (MODE >= 2) ? g_cnt[e] : T;
    int m0  = blockIdx.y * 128;
    if (m0 >= cnt) return;
    int n0  = blockIdx.x * 128;

    __shared__ unsigned As[128][20];   // [row][k], stride-20 -> conflict-free
    __shared__ unsigned Bs[128][20];
    __shared__ int toks[128];

    int tid  = threadIdx.x;
    int warp = tid >> 5, lane = tid & 31;
    int g    = lane >> 2, tig = lane & 3;
    int wm   = warp >> 2, wn = warp & 3;   // warp grid 2 (m) x 4 (n)
    int lr   = tid >> 1,  lk = (tid & 1) * 8;

    if (MODE == 2 || MODE == 3) {
        if (tid < 128) {
            int s = m0 + tid;
            toks[tid] = (s < cnt) ? g_ptok[e * T + s] : g_ptok[e * T];
        }
        __syncthreads();
    }

    const float* Arow;
    if (MODE == 0)      Arow = g_xnorm + (size_t)(m0 + lr) * H;
    else if (MODE == 1) Arow = g_attn  + (size_t)(m0 + lr) * H;
    else if (MODE == 4) Arow = g_act   + (size_t)(e * T + m0 + lr) * F;
    else                Arow = g_xnorm2 + (size_t)toks[lr] * H;

    size_t estride = (MODE == 2 || MODE == 3) ? (size_t)F * H
                   : (MODE == 4) ? (size_t)H * F : 0;
    const float* Brow = B + (size_t)e * estride + (size_t)(n0 + lr) * K;

    float acc[4][4][4];
    #pragma unroll
    for (int mt = 0; mt < 4; mt++)
        #pragma unroll
        for (int nt = 0; nt < 4; nt++)
            #pragma unroll
            for (int r = 0; r < 4; r++) acc[mt][nt][r] = 0.f;

    // prologue: fetch slab 0
    float4 pa0 = *(const float4*)(Arow + lk);
    float4 pa1 = *(const float4*)(Arow + lk + 4);
    float4 pb0 = *(const float4*)(Brow + lk);
    float4 pb1 = *(const float4*)(Brow + lk + 4);

    for (int k0 = 0;;) {
        // stage slab into smem (converting to tf32 bits)
        As[lr][lk+0] = f2tf(pa0.x); As[lr][lk+1] = f2tf(pa0.y);
        As[lr][lk+2] = f2tf(pa0.z); As[lr][lk+3] = f2tf(pa0.w);
        As[lr][lk+4] = f2tf(pa1.x); As[lr][lk+5] = f2tf(pa1.y);
        As[lr][lk+6] = f2tf(pa1.z); As[lr][lk+7] = f2tf(pa1.w);
        Bs[lr][lk+0] = f2tf(pb0.x); Bs[lr][lk+1] = f2tf(pb0.y);
        Bs[lr][lk+2] = f2tf(pb0.z); Bs[lr][lk+3] = f2tf(pb0.w);
        Bs[lr][lk+4] = f2tf(pb1.x); Bs[lr][lk+5] = f2tf(pb1.y);
        Bs[lr][lk+6] = f2tf(pb1.z); Bs[lr][lk+7] = f2tf(pb1.w);
        __syncthreads();

        k0 += 16;
        bool more = (k0 < K);
        if (more) {   // prefetch next slab (overlaps MMA below)
            pa0 = *(const float4*)(Arow + k0 + lk);
            pa1 = *(const float4*)(Arow + k0 + lk + 4);
            pb0 = *(const float4*)(Brow + k0 + lk);
            pb1 = *(const float4*)(Brow + k0 + lk + 4);
        }

        #pragma unroll
        for (int kk = 0; kk < 16; kk += 8) {
            unsigned aR[4][4], bR[4][2];
            #pragma unroll
            for (int mt = 0; mt < 4; mt++) {
                int ar = wm * 64 + mt * 16 + g;
                aR[mt][0] = As[ar][kk + tig];
                aR[mt][1] = As[ar + 8][kk + tig];
                aR[mt][2] = As[ar][kk + tig + 4];
                aR[mt][3] = As[ar + 8][kk + tig + 4];
            }
            #pragma unroll
            for (int nt = 0; nt < 4; nt++) {
                int br = wn * 32 + nt * 8 + g;
                bR[nt][0] = Bs[br][kk + tig];
                bR[nt][1] = Bs[br][kk + tig + 4];
            }
            #pragma unroll
            for (int mt = 0; mt < 4; mt++)
                #pragma unroll
                for (int nt = 0; nt < 4; nt++)
                    mma_tf32(acc[mt][nt], aR[mt], bR[nt]);
        }
        if (!more) break;
        __syncthreads();
    }

    // ------------------------- epilogue (fragment layout) ------------------
    #pragma unroll
    for (int mt = 0; mt < 4; mt++) {
        #pragma unroll
        for (int half = 0; half < 2; half++) {
            int m = m0 + wm * 64 + mt * 16 + g + half * 8;
            if ((MODE >= 2) && m >= cnt) continue;
            #pragma unroll
            for (int nt = 0; nt < 4; nt++) {
                int n = n0 + wn * 32 + nt * 8 + 2 * tig;
                float c0 = acc[mt][nt][half * 2 + 0];
                float c1 = acc[mt][nt][half * 2 + 1];
                if (MODE == 0) {
                    *(float2*)(g_qkv + (size_t)m * QKVN + n) = make_float2(c0, c1);
                } else if (MODE == 1) {
                    float2 r = *(const float2*)(resid + (size_t)m * H + n);
                    *(float2*)(g_x1 + (size_t)m * H + n) =
                        make_float2(c0 + r.x, c1 + r.y);
                } else if (MODE == 2) {
                    *(float2*)(g_act + (size_t)(e * T + m) * F + n) = make_float2(c0, c1);
                } else if (MODE == 3) {
                    float* dst = g_act + (size_t)(e * T + m) * F + n;
                    float2 h3 = *(const float2*)dst;
                    float s0 = 1.f / (1.f + __expf(-c0));
                    float s1 = 1.f / (1.f + __expf(-c1));
                    *(float2*)dst = make_float2(c0 * s0 * h3.x, c1 * s1 * h3.y);
                } else {
                    *(float2*)(g_y + (size_t)(e * T + m) * H + n) = make_float2(c0, c1);
                }
            }
        }
    }
}

__global__ void rope_kernel(const int* __restrict__ pos) {
    int t = blockIdx.x;
    int h = threadIdx.x >> 5, d = threadIdx.x & 31;
    float p = (float)pos[t];
    float inv = powf(10000.f, -(float)d / 32.f);
    float ang = p * inv;
    float c, s;
    sincosf(ang, &s, &c);
    float* base = g_qkv + (size_t)t * QKVN + h * HD;
    float x1 = base[d], x2 = base[d + 32];
    base[d]      = x1 * c - x2 * s;
    base[d + 32] = x2 * c + x1 * s;
}

__global__ __launch_bounds__(256) void attn_kernel() {
    __shared__ float Qs[32][65];
    __shared__ float KVs[64][65];
    __shared__ float Ps[32][65];
    int qt = blockIdx.x, h = blockIdx.y;
    int q0 = qt * 32;
    int kvh = h >> 2;
    int tid = threadIdx.x, tx = tid & 15, ty = tid >> 4;

    #pragma unroll
    for (int it = 0; it < 2; it++) {
        int idx = it * 256 + tid;
        int r = idx >> 4, dc = (idx & 15) << 2;
        float4 v = *(const float4*)(g_qkv + (size_t)(q0 + r) * QKVN + h * HD + dc);
        Qs[r][dc] = v.x; Qs[r][dc + 1] = v.y; Qs[r][dc + 2] = v.z; Qs[r][dc + 3] = v.w;
    }

    float m_i[2] = {-1e30f, -1e30f};
    float l_i[2] = {0.f, 0.f};
    u64 O2[2][2] = {{0ull, 0ull}, {0ull, 0ull}};
    int ktmax = qt >> 1;

    for (int kt = 0; kt <= ktmax; kt++) {
        int k0 = kt * 64;
        bool lastt = (kt == ktmax);
        __syncthreads();
        #pragma unroll
        for (int it = 0; it < 4; it++) {
            int idx = it * 256 + tid;
            int r = idx >> 4, dc = (idx & 15) << 2;
            float4 v = *(const float4*)(g_qkv + (size_t)(k0 + r) * QKVN + 1024 + kvh * HD + dc);
            KVs[r][dc] = v.x; KVs[r][dc + 1] = v.y; KVs[r][dc + 2] = v.z; KVs[r][dc + 3] = v.w;
        }
        __syncthreads();

        u64 sv2[2][2] = {{0ull, 0ull}, {0ull, 0ull}};
        #pragma unroll 8
        for (int d = 0; d < 64; d++) {
            u64 kv01 = pack2(KVs[4 * tx + 0][d], KVs[4 * tx + 1][d]);
            u64 kv23 = pack2(KVs[4 * tx + 2][d], KVs[4 * tx + 3][d]);
            u64 q0d = dup2(Qs[2 * ty + 0][d]);
            u64 q1d = dup2(Qs[2 * ty + 1][d]);
            fma2(sv2[0][0], q0d, kv01); fma2(sv2[0][1], q0d, kv23);
            fma2(sv2[1][0], q1d, kv01); fma2(sv2[1][1], q1d, kv23);
        }
        float sv[2][4];
        unpack2(sv2[0][0], sv[0][0], sv[0][1]); unpack2(sv2[0][1], sv[0][2], sv[0][3]);
        unpack2(sv2[1][0], sv[1][0], sv[1][1]); unpack2(sv2[1][1], sv[1][2], sv[1][3]);

        #pragma unroll
        for (int i = 0; i < 2; i++) {
            int qrow = q0 + 2 * ty + i;
            float p[4], mx = -1e30f;
            #pragma unroll
            for (int j = 0; j < 4; j++) {
                float s = sv[i][j] * 0.125f;
                if (lastt && (k0 + 4 * tx + j > qrow)) s = -1e30f;
                p[j] = s;
                mx = fmaxf(mx, s);
            }
            #pragma unroll
            for (int o = 8; o; o >>= 1) mx = fmaxf(mx, __shfl_xor_sync(0xffffffffu, mx, o));
            float mnew = fmaxf(m_i[i], mx);
            float rs = 0.f;
            #pragma unroll
            for (int j = 0; j < 4; j++) { p[j] = __expf(p[j] - mnew); rs += p[j]; }
            #pragma unroll
            for (int o = 8; o; o >>= 1) rs += __shfl_xor_sync(0xffffffffu, rs, o);
            float fac = __expf(m_i[i] - mnew);
            l_i[i] = l_i[i] * fac + rs;
            m_i[i] = mnew;
            u64 facd = dup2(fac);
            mul2(O2[i][0], O2[i][0], facd);
            mul2(O2[i][1], O2[i][1], facd);
            #pragma unroll
            for (int j = 0; j < 4; j++) Ps[2 * ty + i][4 * tx + j] = p[j];
        }
        __syncthreads();
        #pragma unroll
        for (int it = 0; it < 4; it++) {
            int idx = it * 256 + tid;
            int r = idx >> 4, dc = (idx & 15) << 2;
            float4 v = *(const float4*)(g_qkv + (size_t)(k0 + r) * QKVN + 1280 + kvh * HD + dc);
            KVs[r][dc] = v.x; KVs[r][dc + 1] = v.y; KVs[r][dc + 2] = v.z; KVs[r][dc + 3] = v.w;
        }
        __syncthreads();
        #pragma unroll 8
        for (int k = 0; k < 64; k++) {
            u64 vv01 = pack2(KVs[k][4 * tx + 0], KVs[k][4 * tx + 1]);
            u64 vv23 = pack2(KVs[k][4 * tx + 2], KVs[k][4 * tx + 3]);
            u64 p0 = dup2(Ps[2 * ty + 0][k]);
            u64 p1 = dup2(Ps[2 * ty + 1][k]);
            fma2(O2[0][0], p0, vv01); fma2(O2[0][1], p0, vv23);
            fma2(O2[1][0], p1, vv01); fma2(O2[1][1], p1, vv23);
        }
    }
    #pragma unroll
    for (int i = 0; i < 2; i++) {
        float inv = 1.f / l_i[i];
        int qrow = q0 + 2 * ty + i;
        float o0, o1, o2, o3;
        unpack2(O2[i][0], o0, o1);
        unpack2(O2[i][1], o2, o3);
        float* dst = g_attn + (size_t)qrow * (NH * HD) + h * HD + 4 * tx;
        dst[0] = o0 * inv; dst[1] = o1 * inv; dst[2] = o2 * inv; dst[3] = o3 * inv;
    }
}

__global__ __launch_bounds__(256) void gate_kernel(const float* __restrict__ gate_w) {
    int t = blockIdx.x;
    const float* x = g_xnorm2 + (size_t)t * H;
    int w = threadIdx.x >> 5, lane = threadIdx.x & 31;
    float s = 0.f;
    const float* gw = gate_w + (size_t)w * H;
    for (int i = lane; i < H; i += 32) s += x[i] * gw[i];
    #pragma unroll
    for (int o = 16; o; o >>= 1) s += __shfl_xor_sync(0xffffffffu, s, o);
    __shared__ float logits[NE];
    if (lane == 0) logits[w] = s;
    __syncthreads();
    if (threadIdx.x == 0) {
        float mx = logits[0];
        #pragma unroll
        for (int e = 1; e < NE; e++) mx = fmaxf(mx, logits[e]);
        float p[NE];
        #pragma unroll
        for (int e = 0; e < NE; e++) p[e] = __expf(logits[e] - mx);
        int i1 = 0;
        #pragma unroll
        for (int e = 1; e < NE; e++) if (p[e] > p[i1]) i1 = e;
        int i2 = (i1 == 0) ? 1 : 0;
        #pragma unroll
        for (int e = 0; e < NE; e++) if (e != i1 && p[e] > p[i2]) i2 = e;
        float inv = 1.f / (p[i1] + p[i2]);
        int s0 = atomicAdd(&g_cnt[i1], 1);
        g_ptok[i1 * T + s0] = t;
        g_slot[2 * t + 0] = i1 * T + s0;
        g_gatew[2 * t + 0] = p[i1] * inv;
        int s1 = atomicAdd(&g_cnt[i2], 1);
        g_ptok[i2 * T + s1] = t;
        g_slot[2 * t + 1] = i2 * T + s1;
        g_gatew[2 * t + 1] = p[i2] * inv;
    }
}

// x = x1 + g0*y0 + g1*y1; rmsnorm(x) -> out[0..T*H); x -> out[T*H..) if room.
__global__ __launch_bounds__(256) void combine_kernel(
    const float* __restrict__ w_next, float* __restrict__ out, int write_x)
{
    __shared__ float xs[H];
    int t = blockIdx.x;
    int s0 = g_slot[2 * t + 0], s1 = g_slot[2 * t + 1];
    float g0 = g_gatew[2 * t + 0], g1 = g_gatew[2 * t + 1];
    float ss = 0.f;
    for (int i = threadIdx.x; i < H; i += 256) {
        float v = g_x1[(size_t)t * H + i]
                + g0 * g_y[(size_t)s0 * H + i]
                + g1 * g_y[(size_t)s1 * H + i];
        xs[i] = v;
        if (write_x) out[(size_t)T * H + (size_t)t * H + i] = v;
        ss += v * v;
    }
    float tot = block_sum_256(ss);
    float scale = rsqrtf(tot / (float)H + EPS);
    __syncthreads();
    for (int i = threadIdx.x; i < H; i += 256)
        out[(size_t)t * H + i] = xs[i] * scale * w_next[i];
}

// ------------------------------------------------------------------- launch
extern "C" void kernel_launch(void* const* d_in, const int* in_sizes, int n_in,
                              void* d_out, int out_size)
{
    const int*   positions = nullptr;
    const float* hidden = nullptr;
    const float* w_qkv = nullptr;
    const float* w_o = nullptr;
    const float* gate_w = nullptr;
    const float* norms[3] = {nullptr, nullptr, nullptr};
    const float* big[3]   = {nullptr, nullptr, nullptr};
    int nn = 0, nb = 0;
    for (int i = 0; i < n_in; i++) {
        switch (in_sizes[i]) {
            case 2048:     positions = (const int*)d_in[i];   break;
            case 2097152:  hidden    = (const float*)d_in[i]; break;
            case 1572864:  w_qkv     = (const float*)d_in[i]; break;
            case 1048576:  w_o       = (const float*)d_in[i]; break;
            case 8192:     gate_w    = (const float*)d_in[i]; break;
            case 1024:     if (nn < 3) norms[nn++] = (const float*)d_in[i]; break;
            case 16777216: if (nb < 3) big[nb++]   = (const float*)d_in[i]; break;
            default: break;
        }
    }
    const float* norm_in   = norms[0];
    const float* norm_post = norms[1];
    const float* norm_next = norms[2];
    const float* w1 = big[0];
    const float* w2 = big[1];
    const float* w3 = big[2];
    float* out = (float*)d_out;

    int write_x = (out_size == 2 * T * H || out_size == 2 * T * H * 4) ? 1 : 0;

    zero_cnt_kernel<<<1, 32>>>();
    rmsnorm_kernel<0><<<T, 256>>>(hidden, norm_in);
    gemm_tc<0><<<dim3(QKVN / 128, T / 128), 256>>>(w_qkv, nullptr);
    rope_kernel<<<T, (NH + NKV) * 32>>>(positions);
    attn_kernel<<<dim3(T / 32, NH), 256>>>();
    gemm_tc<1><<<dim3(H / 128, T / 128), 256>>>(w_o, hidden);
    rmsnorm_kernel<1><<<T, 256>>>(nullptr, norm_post);
    gate_kernel<<<T, 256>>>(gate_w);
    gemm_tc<2><<<dim3(F / 128, T / 128, NE), 256>>>(w3, nullptr);
    gemm_tc<3><<<dim3(F / 128, T / 128, NE), 256>>>(w1, nullptr);
    gemm_tc<4><<<dim3(H / 128, T / 128, NE), 256>>>(w2, nullptr);
    combine_kernel<<<T, 256>>>(norm_next, out, write_x);
}

// round 14
// speedup vs baseline: 2.8045x; 1.4614x over previous
#include <cuda_runtime.h>
#include <math.h>

constexpr int T   = 2048;
constexpr int H   = 1024;
constexpr int NH  = 16;
constexpr int NKV = 4;
constexpr int HD  = 64;
constexpr int NE  = 8;
constexpr int F   = 2048;
constexpr int QKVN = (NH + 2 * NKV) * HD;  // 1536
constexpr float EPS = 1e-5f;

// ---- tf32 tensor-core helpers ---------------------------------------------
__device__ __forceinline__ unsigned f2tf(float x) {
    unsigned r; asm("cvt.rna.tf32.f32 %0, %1;" : "=r"(r) : "f"(x)); return r;
}
__device__ __forceinline__ void mma_tf32(float* c, const unsigned* a, const unsigned* b) {
    asm("mma.sync.aligned.m16n8k8.row.col.f32.tf32.tf32.f32 "
        "{%0,%1,%2,%3}, {%4,%5,%6,%7}, {%8,%9}, {%0,%1,%2,%3};"
        : "+f"(c[0]), "+f"(c[1]), "+f"(c[2]), "+f"(c[3])
        : "r"(a[0]), "r"(a[1]), "r"(a[2]), "r"(a[3]), "r"(b[0]), "r"(b[1]));
}

// ---- scratch: device globals, referenced ONLY inside device code ----------
__device__ float g_xnorm[T * H];
__device__ float g_qkv[T * QKVN];
__device__ float g_attn[T * NH * HD];
__device__ float g_x1[T * H];
__device__ float g_xnorm2[T * H];
__device__ int   g_cnt[NE];
__device__ int   g_ptok[NE * T];
__device__ int   g_slot[2 * T];
__device__ float g_gatew[2 * T];
__device__ float g_act[NE * T * F];
__device__ float g_y[NE * T * H];

// ---------------------------------------------------------------- utilities
__device__ __forceinline__ float block_sum_256(float v) {
    __shared__ float red[8];
    #pragma unroll
    for (int o = 16; o; o >>= 1) v += __shfl_xor_sync(0xffffffffu, v, o);
    if ((threadIdx.x & 31) == 0) red[threadIdx.x >> 5] = v;
    __syncthreads();
    if (threadIdx.x == 0) {
        float s = 0.f;
        #pragma unroll
        for (int i = 0; i < 8; i++) s += red[i];
        red[0] = s;
    }
    __syncthreads();
    float r = red[0];
    __syncthreads();
    return r;
}

// ------------------------------------------------------------------ kernels
__global__ void zero_cnt_kernel() {
    if (threadIdx.x < NE) g_cnt[threadIdx.x] = 0;
}

template <int MODE>
__global__ __launch_bounds__(256) void rmsnorm_kernel(
    const float* __restrict__ xin, const float* __restrict__ w)
{
    int t = blockIdx.x;
    const float* x = (MODE == 0) ? xin : (const float*)g_x1;
    float* out = (MODE == 0) ? g_xnorm : g_xnorm2;
    const float* xr = x + (size_t)t * H;
    float ss = 0.f;
    for (int i = threadIdx.x; i < H; i += 256) { float v = xr[i]; ss += v * v; }
    float tot = block_sum_256(ss);
    float scale = rsqrtf(tot / (float)H + EPS);
    for (int i = threadIdx.x; i < H; i += 256)
        out[(size_t)t * H + i] = xr[i] * scale * w[i];
}

// ---------------- unified 128x128 TF32 tensor-core GEMM --------------------
// MODE 0: g_qkv  = g_xnorm * w_qkv^T                (N=QKVN, K=H)
// MODE 1: g_x1   = g_attn  * w_o^T + resid          (N=H,    K=H)
// MODE 2: g_act  = Xg      * w3^T   (gathered rows) (N=F,    K=H)
// MODE 3: g_act  = silu(Xg * w1^T) * g_act          (N=F,    K=H)
// MODE 4: g_y    = g_act   * w2^T                   (N=H,    K=F)
template <int MODE>
__global__ __launch_bounds__(256) void gemm_tc(
    const float* __restrict__ B, const float* __restrict__ resid)
{
    constexpr int K = (MODE == 4) ? F : H;

    int e   = (MODE >= 2) ? blockIdx.z : 0;
    int cnt = (MODE >= 2) ? g_cnt[e] : T;
    int m0  = blockIdx.y * 128;
    if (m0 >= cnt) return;
    int n0  = blockIdx.x * 128;

    __shared__ unsigned As[128][20];
    __shared__ unsigned Bs[128][20];
    __shared__ int toks[128];

    int tid  = threadIdx.x;
    int warp = tid >> 5, lane = tid & 31;
    int g    = lane >> 2, tig = lane & 3;
    int wm   = warp >> 2, wn = warp & 3;
    int lr   = tid >> 1,  lk = (tid & 1) * 8;

    if (MODE == 2 || MODE == 3) {
        if (tid < 128) {
            int s = m0 + tid;
            toks[tid] = (s < cnt) ? g_ptok[e * T + s] : g_ptok[e * T];
        }
        __syncthreads();
    }

    const float* Arow;
    if (MODE == 0)      Arow = g_xnorm + (size_t)(m0 + lr) * H;
    else if (MODE == 1) Arow = g_attn  + (size_t)(m0 + lr) * H;
    else if (MODE == 4) Arow = g_act   + (size_t)(e * T + m0 + lr) * F;
    else                Arow = g_xnorm2 + (size_t)toks[lr] * H;

    size_t estride = (MODE == 2 || MODE == 3) ? (size_t)F * H
                   : (MODE == 4) ? (size_t)H * F : 0;
    const float* Brow = B + (size_t)e * estride + (size_t)(n0 + lr) * K;

    float acc[4][4][4];
    #pragma unroll
    for (int mt = 0; mt < 4; mt++)
        #pragma unroll
        for (int nt = 0; nt < 4; nt++)
            #pragma unroll
            for (int r = 0; r < 4; r++) acc[mt][nt][r] = 0.f;

    float4 pa0 = *(const float4*)(Arow + lk);
    float4 pa1 = *(const float4*)(Arow + lk + 4);
    float4 pb0 = *(const float4*)(Brow + lk);
    float4 pb1 = *(const float4*)(Brow + lk + 4);

    for (int k0 = 0;;) {
        As[lr][lk+0] = f2tf(pa0.x); As[lr][lk+1] = f2tf(pa0.y);
        As[lr][lk+2] = f2tf(pa0.z); As[lr][lk+3] = f2tf(pa0.w);
        As[lr][lk+4] = f2tf(pa1.x); As[lr][lk+5] = f2tf(pa1.y);
        As[lr][lk+6] = f2tf(pa1.z); As[lr][lk+7] = f2tf(pa1.w);
        Bs[lr][lk+0] = f2tf(pb0.x); Bs[lr][lk+1] = f2tf(pb0.y);
        Bs[lr][lk+2] = f2tf(pb0.z); Bs[lr][lk+3] = f2tf(pb0.w);
        Bs[lr][lk+4] = f2tf(pb1.x); Bs[lr][lk+5] = f2tf(pb1.y);
        Bs[lr][lk+6] = f2tf(pb1.z); Bs[lr][lk+7] = f2tf(pb1.w);
        __syncthreads();

        k0 += 16;
        bool more = (k0 < K);
        if (more) {
            pa0 = *(const float4*)(Arow + k0 + lk);
            pa1 = *(const float4*)(Arow + k0 + lk + 4);
            pb0 = *(const float4*)(Brow + k0 + lk);
            pb1 = *(const float4*)(Brow + k0 + lk + 4);
        }

        #pragma unroll
        for (int kk = 0; kk < 16; kk += 8) {
            unsigned aR[4][4], bR[4][2];
            #pragma unroll
            for (int mt = 0; mt < 4; mt++) {
                int ar = wm * 64 + mt * 16 + g;
                aR[mt][0] = As[ar][kk + tig];
                aR[mt][1] = As[ar + 8][kk + tig];
                aR[mt][2] = As[ar][kk + tig + 4];
                aR[mt][3] = As[ar + 8][kk + tig + 4];
            }
            #pragma unroll
            for (int nt = 0; nt < 4; nt++) {
                int br = wn * 32 + nt * 8 + g;
                bR[nt][0] = Bs[br][kk + tig];
                bR[nt][1] = Bs[br][kk + tig + 4];
            }
            #pragma unroll
            for (int mt = 0; mt < 4; mt++)
                #pragma unroll
                for (int nt = 0; nt < 4; nt++)
                    mma_tf32(acc[mt][nt], aR[mt], bR[nt]);
        }
        if (!more) break;
        __syncthreads();
    }

    #pragma unroll
    for (int mt = 0; mt < 4; mt++) {
        #pragma unroll
        for (int half = 0; half < 2; half++) {
            int m = m0 + wm * 64 + mt * 16 + g + half * 8;
            if ((MODE >= 2) && m >= cnt) continue;
            #pragma unroll
            for (int nt = 0; nt < 4; nt++) {
                int n = n0 + wn * 32 + nt * 8 + 2 * tig;
                float c0 = acc[mt][nt][half * 2 + 0];
                float c1 = acc[mt][nt][half * 2 + 1];
                if (MODE == 0) {
                    *(float2*)(g_qkv + (size_t)m * QKVN + n) = make_float2(c0, c1);
                } else if (MODE == 1) {
                    float2 r = *(const float2*)(resid + (size_t)m * H + n);
                    *(float2*)(g_x1 + (size_t)m * H + n) =
                        make_float2(c0 + r.x, c1 + r.y);
                } else if (MODE == 2) {
                    *(float2*)(g_act + (size_t)(e * T + m) * F + n) = make_float2(c0, c1);
                } else if (MODE == 3) {
                    float* dst = g_act + (size_t)(e * T + m) * F + n;
                    float2 h3 = *(const float2*)dst;
                    float s0 = 1.f / (1.f + __expf(-c0));
                    float s1 = 1.f / (1.f + __expf(-c1));
                    *(float2*)dst = make_float2(c0 * s0 * h3.x, c1 * s1 * h3.y);
                } else {
                    *(float2*)(g_y + (size_t)(e * T + m) * H + n) = make_float2(c0, c1);
                }
            }
        }
    }
}

__global__ void rope_kernel(const int* __restrict__ pos) {
    int t = blockIdx.x;
    int h = threadIdx.x >> 5, d = threadIdx.x & 31;
    float p = (float)pos[t];
    float inv = powf(10000.f, -(float)d / 32.f);
    float ang = p * inv;
    float c, s;
    sincosf(ang, &s, &c);
    float* base = g_qkv + (size_t)t * QKVN + h * HD;
    float x1 = base[d], x2 = base[d + 32];
    base[d]      = x1 * c - x2 * s;
    base[d + 32] = x2 * c + x1 * s;
}

// ---------------- TF32 tensor-core flash attention -------------------------
// block = (64-query tile, head); 4 warps x 16 rows. m16n8k8 everywhere.
__global__ __launch_bounds__(128) void attn_tc() {
    __shared__ unsigned KVs[64][68];   // Q staging -> K tile -> V^T tile
    __shared__ unsigned Ps[64][68];    // P (tf32 bits) for the PV mma
    int qt = (int)gridDim.x - 1 - blockIdx.x;   // longest blocks first
    int h = blockIdx.y;
    int q0 = qt * 64;
    int kvh = h >> 2;
    int tid = threadIdx.x, warp = tid >> 5, lane = tid & 31;
    int g = lane >> 2, tig = lane & 3;
    int wrow = warp * 16;
    int ldr = tid >> 1, ldk = (tid & 1) * 32;

    // stage Q (pre-scaled by 1/8), pull A-fragments to registers
    {
        const float* src = g_qkv + (size_t)(q0 + ldr) * QKVN + h * HD + ldk;
        #pragma unroll
        for (int i = 0; i < 32; i += 4) {
            float4 v = *(const float4*)(src + i);
            KVs[ldr][ldk+i+0] = f2tf(v.x * 0.125f);
            KVs[ldr][ldk+i+1] = f2tf(v.y * 0.125f);
            KVs[ldr][ldk+i+2] = f2tf(v.z * 0.125f);
            KVs[ldr][ldk+i+3] = f2tf(v.w * 0.125f);
        }
    }
    __syncthreads();
    unsigned qf[8][4];
    #pragma unroll
    for (int kk = 0; kk < 8; kk++) {
        qf[kk][0] = KVs[wrow + g][kk * 8 + tig];
        qf[kk][1] = KVs[wrow + g + 8][kk * 8 + tig];
        qf[kk][2] = KVs[wrow + g][kk * 8 + tig + 4];
        qf[kk][3] = KVs[wrow + g + 8][kk * 8 + tig + 4];
    }

    float m_i[2] = {-1e30f, -1e30f};
    float l_i[2] = {0.f, 0.f};
    float O[8][4];
    #pragma unroll
    for (int nt = 0; nt < 8; nt++)
        O[nt][0] = O[nt][1] = O[nt][2] = O[nt][3] = 0.f;

    for (int kt = 0; kt <= qt; kt++) {
        int k0 = kt * 64;
        __syncthreads();   // prev PV done with KVs/Ps
        {   // K tile [key][d]
            const float* src = g_qkv + (size_t)(k0 + ldr) * QKVN + 1024 + kvh * HD + ldk;
            #pragma unroll
            for (int i = 0; i < 32; i += 4) {
                float4 v = *(const float4*)(src + i);
                KVs[ldr][ldk+i+0] = f2tf(v.x);
                KVs[ldr][ldk+i+1] = f2tf(v.y);
                KVs[ldr][ldk+i+2] = f2tf(v.z);
                KVs[ldr][ldk+i+3] = f2tf(v.w);
            }
        }
        __syncthreads();

        float S[8][4];
        #pragma unroll
        for (int nt = 0; nt < 8; nt++)
            S[nt][0] = S[nt][1] = S[nt][2] = S[nt][3] = 0.f;
        #pragma unroll
        for (int kk = 0; kk < 8; kk++) {
            #pragma unroll
            for (int nt = 0; nt < 8; nt++) {
                unsigned b[2] = {KVs[nt * 8 + g][kk * 8 + tig],
                                 KVs[nt * 8 + g][kk * 8 + tig + 4]};
                mma_tf32(S[nt], qf[kk], b);
            }
        }

        if (kt == qt) {   // diagonal tile: causal mask (relative cols/rows)
            #pragma unroll
            for (int nt = 0; nt < 8; nt++) {
                int colb = nt * 8 + 2 * tig;
                if (colb     > wrow + g)     S[nt][0] = -1e30f;
                if (colb + 1 > wrow + g)     S[nt][1] = -1e30f;
                if (colb     > wrow + g + 8) S[nt][2] = -1e30f;
                if (colb + 1 > wrow + g + 8) S[nt][3] = -1e30f;
            }
        }
        float mx0 = -1e30f, mx1 = -1e30f;
        #pragma unroll
        for (int nt = 0; nt < 8; nt++) {
            mx0 = fmaxf(mx0, fmaxf(S[nt][0], S[nt][1]));
            mx1 = fmaxf(mx1, fmaxf(S[nt][2], S[nt][3]));
        }
        #pragma unroll
        for (int o = 1; o <= 2; o <<= 1) {
            mx0 = fmaxf(mx0, __shfl_xor_sync(0xffffffffu, mx0, o));
            mx1 = fmaxf(mx1, __shfl_xor_sync(0xffffffffu, mx1, o));
        }
        float mn0 = fmaxf(m_i[0], mx0), mn1 = fmaxf(m_i[1], mx1);
        float fac0 = __expf(m_i[0] - mn0), fac1 = __expf(m_i[1] - mn1);
        float rs0 = 0.f, rs1 = 0.f;
        #pragma unroll
        for (int nt = 0; nt < 8; nt++) {
            int colb = nt * 8 + 2 * tig;
            float p00 = __expf(S[nt][0] - mn0);
            float p01 = __expf(S[nt][1] - mn0);
            float p10 = __expf(S[nt][2] - mn1);
            float p11 = __expf(S[nt][3] - mn1);
            rs0 += p00 + p01; rs1 += p10 + p11;
            Ps[wrow + g][colb]     = f2tf(p00);
            Ps[wrow + g][colb + 1] = f2tf(p01);
            Ps[wrow + g + 8][colb]     = f2tf(p10);
            Ps[wrow + g + 8][colb + 1] = f2tf(p11);
        }
        #pragma unroll
        for (int o = 1; o <= 2; o <<= 1) {
            rs0 += __shfl_xor_sync(0xffffffffu, rs0, o);
            rs1 += __shfl_xor_sync(0xffffffffu, rs1, o);
        }
        l_i[0] = l_i[0] * fac0 + rs0;
        l_i[1] = l_i[1] * fac1 + rs1;
        m_i[0] = mn0; m_i[1] = mn1;
        #pragma unroll
        for (int nt = 0; nt < 8; nt++) {
            O[nt][0] *= fac0; O[nt][1] *= fac0;
            O[nt][2] *= fac1; O[nt][3] *= fac1;
        }

        __syncthreads();   // K reads done; Ps visible
        {   // V^T tile: KVs[d][key]
            const float* src = g_qkv + (size_t)(k0 + ldr) * QKVN + 1280 + kvh * HD + ldk;
            #pragma unroll
            for (int i = 0; i < 32; i += 4) {
                float4 v = *(const float4*)(src + i);
                KVs[ldk+i+0][ldr] = f2tf(v.x);
                KVs[ldk+i+1][ldr] = f2tf(v.y);
                KVs[ldk+i+2][ldr] = f2tf(v.z);
                KVs[ldk+i+3][ldr] = f2tf(v.w);
            }
        }
        __syncthreads();
        #pragma unroll
        for (int kk = 0; kk < 8; kk++) {
            unsigned af[4] = {Ps[wrow + g][kk * 8 + tig],
                              Ps[wrow + g + 8][kk * 8 + tig],
                              Ps[wrow + g][kk * 8 + tig + 4],
                              Ps[wrow + g + 8][kk * 8 + tig + 4]};
            #pragma unroll
            for (int nt = 0; nt < 8; nt++) {
                unsigned b[2] = {KVs[nt * 8 + g][kk * 8 + tig],
                                 KVs[nt * 8 + g][kk * 8 + tig + 4]};
                mma_tf32(O[nt], af, b);
            }
        }
    }

    float inv0 = 1.f / l_i[0], inv1 = 1.f / l_i[1];
    #pragma unroll
    for (int nt = 0; nt < 8; nt++) {
        int n = h * HD + nt * 8 + 2 * tig;
        *(float2*)(g_attn + (size_t)(q0 + wrow + g) * (NH * HD) + n) =
            make_float2(O[nt][0] * inv0, O[nt][1] * inv0);
        *(float2*)(g_attn + (size_t)(q0 + wrow + g + 8) * (NH * HD) + n) =
            make_float2(O[nt][2] * inv1, O[nt][3] * inv1);
    }
}

__global__ __launch_bounds__(256) void gate_kernel(const float* __restrict__ gate_w) {
    int t = blockIdx.x;
    const float* x = g_xnorm2 + (size_t)t * H;
    int w = threadIdx.x >> 5, lane = threadIdx.x & 31;
    float s = 0.f;
    const float* gw = gate_w + (size_t)w * H;
    for (int i = lane; i < H; i += 32) s += x[i] * gw[i];
    #pragma unroll
    for (int o = 16; o; o >>= 1) s += __shfl_xor_sync(0xffffffffu, s, o);
    __shared__ float logits[NE];
    if (lane == 0) logits[w] = s;
    __syncthreads();
    if (threadIdx.x == 0) {
        float mx = logits[0];
        #pragma unroll
        for (int e = 1; e < NE; e++) mx = fmaxf(mx, logits[e]);
        float p[NE];
        #pragma unroll
        for (int e = 0; e < NE; e++) p[e] = __expf(logits[e] - mx);
        int i1 = 0;
        #pragma unroll
        for (int e = 1; e < NE; e++) if (p[e] > p[i1]) i1 = e;
        int i2 = (i1 == 0) ? 1 : 0;
        #pragma unroll
        for (int e = 0; e < NE; e++) if (e != i1 && p[e] > p[i2]) i2 = e;
        float inv = 1.f / (p[i1] + p[i2]);
        int s0 = atomicAdd(&g_cnt[i1], 1);
        g_ptok[i1 * T + s0] = t;
        g_slot[2 * t + 0] = i1 * T + s0;
        g_gatew[2 * t + 0] = p[i1] * inv;
        int s1 = atomicAdd(&g_cnt[i2], 1);
        g_ptok[i2 * T + s1] = t;
        g_slot[2 * t + 1] = i2 * T + s1;
        g_gatew[2 * t + 1] = p[i2] * inv;
    }
}

// x = x1 + g0*y0 + g1*y1; rmsnorm(x) -> out[0..T*H); x -> out[T*H..) if room.
__global__ __launch_bounds__(256) void combine_kernel(
    const float* __restrict__ w_next, float* __restrict__ out, int write_x)
{
    __shared__ float xs[H];
    int t = blockIdx.x;
    int s0 = g_slot[2 * t + 0], s1 = g_slot[2 * t + 1];
    float g0 = g_gatew[2 * t + 0], g1 = g_gatew[2 * t + 1];
    float ss = 0.f;
    for (int i = threadIdx.x; i < H; i += 256) {
        float v = g_x1[(size_t)t * H + i]
                + g0 * g_y[(size_t)s0 * H + i]
                + g1 * g_y[(size_t)s1 * H + i];
        xs[i] = v;
        if (write_x) out[(size_t)T * H + (size_t)t * H + i] = v;
        ss += v * v;
    }
    float tot = block_sum_256(ss);
    float scale = rsqrtf(tot / (float)H + EPS);
    __syncthreads();
    for (int i = threadIdx.x; i < H; i += 256)
        out[(size_t)t * H + i] = xs[i] * scale * w_next[i];
}

// ------------------------------------------------------------------- launch
extern "C" void kernel_launch(void* const* d_in, const int* in_sizes, int n_in,
                              void* d_out, int out_size)
{
    const int*   positions = nullptr;
    const float* hidden = nullptr;
    const float* w_qkv = nullptr;
    const float* w_o = nullptr;
    const float* gate_w = nullptr;
    const float* norms[3] = {nullptr, nullptr, nullptr};
    const float* big[3]   = {nullptr, nullptr, nullptr};
    int nn = 0, nb = 0;
    for (int i = 0; i < n_in; i++) {
        switch (in_sizes[i]) {
            case 2048:     positions = (const int*)d_in[i];   break;
            case 2097152:  hidden    = (const float*)d_in[i]; break;
            case 1572864:  w_qkv     = (const float*)d_in[i]; break;
            case 1048576:  w_o       = (const float*)d_in[i]; break;
            case 8192:     gate_w    = (const float*)d_in[i]; break;
            case 1024:     if (nn < 3) norms[nn++] = (const float*)d_in[i]; break;
            case 16777216: if (nb < 3) big[nb++]   = (const float*)d_in[i]; break;
            default: break;
        }
    }
    const float* norm_in   = norms[0];
    const float* norm_post = norms[1];
    const float* norm_next = norms[2];
    const float* w1 = big[0];
    const float* w2 = big[1];
    const float* w3 = big[2];
    float* out = (float*)d_out;

    int write_x = (out_size == 2 * T * H || out_size == 2 * T * H * 4) ? 1 : 0;

    zero_cnt_kernel<<<1, 32>>>();
    rmsnorm_kernel<0><<<T, 256>>>(hidden, norm_in);
    gemm_tc<0><<<dim3(QKVN / 128, T / 128), 256>>>(w_qkv, nullptr);
    rope_kernel<<<T, (NH + NKV) * 32>>>(positions);
    attn_tc<<<dim3(T / 64, NH), 128>>>();
    gemm_tc<1><<<dim3(H / 128, T / 128), 256>>>(w_o, hidden);
    rmsnorm_kernel<1><<<T, 256>>>(nullptr, norm_post);
    gate_kernel<<<T, 256>>>(gate_w);
    gemm_tc<2><<<dim3(F / 128, T / 128, NE), 256>>>(w3, nullptr);
    gemm_tc<3><<<dim3(F / 128, T / 128, NE), 256>>>(w1, nullptr);
    gemm_tc<4><<<dim3(H / 128, T / 128, NE), 256>>>(w2, nullptr);
    combine_kernel<<<T, 256>>>(norm_next, out, write_x);
}

// round 15
// speedup vs baseline: 3.8088x; 1.3581x over previous
#include <cuda_runtime.h>
#include <math.h>

constexpr int T   = 2048;
constexpr int H   = 1024;
constexpr int NH  = 16;
constexpr int NKV = 4;
constexpr int HD  = 64;
constexpr int NE  = 8;
constexpr int F   = 2048;
constexpr int QKVN = (NH + 2 * NKV) * HD;  // 1536
constexpr float EPS = 1e-5f;

// ---- tf32 helpers (attention) ---------------------------------------------
__device__ __forceinline__ unsigned f2tf(float x) {
    unsigned r; asm("cvt.rna.tf32.f32 %0, %1;" : "=r"(r) : "f"(x)); return r;
}
__device__ __forceinline__ void mma_tf32(float* c, const unsigned* a, const unsigned* b) {
    asm("mma.sync.aligned.m16n8k8.row.col.f32.tf32.tf32.f32 "
        "{%0,%1,%2,%3}, {%4,%5,%6,%7}, {%8,%9}, {%0,%1,%2,%3};"
        : "+f"(c[0]), "+f"(c[1]), "+f"(c[2]), "+f"(c[3])
        : "r"(a[0]), "r"(a[1]), "r"(a[2]), "r"(a[3]), "r"(b[0]), "r"(b[1]));
}

// ---- bf16 helpers (GEMMs) -------------------------------------------------
__device__ __forceinline__ unsigned f2bf2(float lo, float hi) {
    unsigned r;  // packed.lo = bf16(lo), packed.hi = bf16(hi)
    asm("cvt.rn.bf16x2.f32 %0, %1, %2;" : "=r"(r) : "f"(hi), "f"(lo));
    return r;
}
__device__ __forceinline__ void mma_bf16(float* c, const unsigned* a, const unsigned* b) {
    asm("mma.sync.aligned.m16n8k16.row.col.f32.bf16.bf16.f32 "
        "{%0,%1,%2,%3}, {%4,%5,%6,%7}, {%8,%9}, {%0,%1,%2,%3};"
        : "+f"(c[0]), "+f"(c[1]), "+f"(c[2]), "+f"(c[3])
        : "r"(a[0]), "r"(a[1]), "r"(a[2]), "r"(a[3]), "r"(b[0]), "r"(b[1]));
}

// ---- scratch: device globals, referenced ONLY inside device code ----------
__device__ float g_xnorm[T * H];
__device__ float g_qkv[T * QKVN];
__device__ float g_attn[T * NH * HD];
__device__ float g_x1[T * H];
__device__ float g_xnorm2[T * H];
__device__ int   g_cnt[NE];
__device__ int   g_ptok[NE * T];
__device__ int   g_slot[2 * T];
__device__ float g_gatew[2 * T];
__device__ float g_act[NE * T * F];
__device__ float g_y[NE * T * H];

// ---------------------------------------------------------------- utilities
__device__ __forceinline__ float block_sum_256(float v) {
    __shared__ float red[8];
    #pragma unroll
    for (int o = 16; o; o >>= 1) v += __shfl_xor_sync(0xffffffffu, v, o);
    if ((threadIdx.x & 31) == 0) red[threadIdx.x >> 5] = v;
    __syncthreads();
    if (threadIdx.x == 0) {
        float s = 0.f;
        #pragma unroll
        for (int i = 0; i < 8; i++) s += red[i];
        red[0] = s;
    }
    __syncthreads();
    float r = red[0];
    __syncthreads();
    return r;
}

// ------------------------------------------------------------------ kernels
__global__ void zero_cnt_kernel() {
    if (threadIdx.x < NE) g_cnt[threadIdx.x] = 0;
}

template <int MODE>
__global__ __launch_bounds__(256) void rmsnorm_kernel(
    const float* __restrict__ xin, const float* __restrict__ w)
{
    int t = blockIdx.x;
    const float* x = (MODE == 0) ? xin : (const float*)g_x1;
    float* out = (MODE == 0) ? g_xnorm : g_xnorm2;
    const float* xr = x + (size_t)t * H;
    float ss = 0.f;
    for (int i = threadIdx.x; i < H; i += 256) { float v = xr[i]; ss += v * v; }
    float tot = block_sum_256(ss);
    float scale = rsqrtf(tot / (float)H + EPS);
    for (int i = threadIdx.x; i < H; i += 256)
        out[(size_t)t * H + i] = xr[i] * scale * w[i];
}

// ------------- unified 128x128 bf16 m16n8k16 tensor-core GEMM --------------
// MODE 0: g_qkv  = g_xnorm * w_qkv^T                (N=QKVN, K=H)
// MODE 1: g_x1   = g_attn  * w_o^T + resid          (N=H,    K=H)
// MODE 2: g_act  = Xg      * w3^T   (gathered rows) (N=F,    K=H)
// MODE 3: g_act  = silu(Xg * w1^T) * g_act          (N=F,    K=H)
// MODE 4: g_y    = g_act   * w2^T                   (N=H,    K=F)
template <int MODE>
__global__ __launch_bounds__(256) void gemm_tc(
    const float* __restrict__ B, const float* __restrict__ resid)
{
    constexpr int K = (MODE == 4) ? F : H;

    int e   = (MODE >= 2) ? blockIdx.z : 0;
    int cnt = (MODE >= 2) ? g_cnt[e] : T;
    int m0  = blockIdx.y * 128;
    if (m0 >= cnt) return;
    int n0  = blockIdx.x * 128;

    // packed bf16x2, [row][k/2]; 16 packed per K=32 slab; stride 20 -> no conflicts
    __shared__ unsigned As[128][20];
    __shared__ unsigned Bs[128][20];
    __shared__ int toks[128];

    int tid  = threadIdx.x;
    int warp = tid >> 5, lane = tid & 31;
    int g    = lane >> 2, tig = lane & 3;
    int wm   = warp >> 2, wn = warp & 3;   // warp grid 2(m) x 4(n)
    int lr   = tid >> 1,  lk = (tid & 1) * 16;   // f32 k-offset of this thread's load

    if (MODE == 2 || MODE == 3) {
        if (tid < 128) {
            int s = m0 + tid;
            toks[tid] = (s < cnt) ? g_ptok[e * T + s] : g_ptok[e * T];
        }
        __syncthreads();
    }

    const float* Arow;
    if (MODE == 0)      Arow = g_xnorm + (size_t)(m0 + lr) * H;
    else if (MODE == 1) Arow = g_attn  + (size_t)(m0 + lr) * H;
    else if (MODE == 4) Arow = g_act   + (size_t)(e * T + m0 + lr) * F;
    else                Arow = g_xnorm2 + (size_t)toks[lr] * H;

    size_t estride = (MODE == 2 || MODE == 3) ? (size_t)F * H
                   : (MODE == 4) ? (size_t)H * F : 0;
    const float* Brow = B + (size_t)e * estride + (size_t)(n0 + lr) * K;

    float acc[4][4][4];
    #pragma unroll
    for (int mt = 0; mt < 4; mt++)
        #pragma unroll
        for (int nt = 0; nt < 4; nt++)
            #pragma unroll
            for (int r = 0; r < 4; r++) acc[mt][nt][r] = 0.f;

    // prologue: fetch K-slab 0 (32 wide; 16 f32 per thread per operand)
    float4 pa[4], pb[4];
    #pragma unroll
    for (int i = 0; i < 4; i++) {
        pa[i] = *(const float4*)(Arow + lk + i * 4);
        pb[i] = *(const float4*)(Brow + lk + i * 4);
    }

    for (int k0 = 0;;) {
        int kp = lk >> 1;   // packed offset (8 packed per thread)
        #pragma unroll
        for (int i = 0; i < 4; i++) {
            As[lr][kp + 2*i    ] = f2bf2(pa[i].x, pa[i].y);
            As[lr][kp + 2*i + 1] = f2bf2(pa[i].z, pa[i].w);
            Bs[lr][kp + 2*i    ] = f2bf2(pb[i].x, pb[i].y);
            Bs[lr][kp + 2*i + 1] = f2bf2(pb[i].z, pb[i].w);
        }
        __syncthreads();

        k0 += 32;
        bool more = (k0 < K);
        if (more) {
            #pragma unroll
            for (int i = 0; i < 4; i++) {
                pa[i] = *(const float4*)(Arow + k0 + lk + i * 4);
                pb[i] = *(const float4*)(Brow + k0 + lk + i * 4);
            }
        }

        #pragma unroll
        for (int kk = 0; kk < 2; kk++) {   // two k16 steps per K=32 slab
            unsigned aR[4][4], bR[4][2];
            #pragma unroll
            for (int mt = 0; mt < 4; mt++) {
                int ar = wm * 64 + mt * 16 + g;
                aR[mt][0] = As[ar][kk * 8 + tig];
                aR[mt][1] = As[ar + 8][kk * 8 + tig];
                aR[mt][2] = As[ar][kk * 8 + tig + 4];
                aR[mt][3] = As[ar + 8][kk * 8 + tig + 4];
            }
            #pragma unroll
            for (int nt = 0; nt < 4; nt++) {
                int br = wn * 32 + nt * 8 + g;
                bR[nt][0] = Bs[br][kk * 8 + tig];
                bR[nt][1] = Bs[br][kk * 8 + tig + 4];
            }
            #pragma unroll
            for (int mt = 0; mt < 4; mt++)
                #pragma unroll
                for (int nt = 0; nt < 4; nt++)
                    mma_bf16(acc[mt][nt], aR[mt], bR[nt]);
        }
        if (!more) break;
        __syncthreads();
    }

    // ------------------------- epilogue (fragment layout) ------------------
    #pragma unroll
    for (int mt = 0; mt < 4; mt++) {
        #pragma unroll
        for (int half = 0; half < 2; half++) {
            int m = m0 + wm * 64 + mt * 16 + g + half * 8;
            if ((MODE >= 2) && m >= cnt) continue;
            #pragma unroll
            for (int nt = 0; nt < 4; nt++) {
                int n = n0 + wn * 32 + nt * 8 + 2 * tig;
                float c0 = acc[mt][nt][half * 2 + 0];
                float c1 = acc[mt][nt][half * 2 + 1];
                if (MODE == 0) {
                    *(float2*)(g_qkv + (size_t)m * QKVN + n) = make_float2(c0, c1);
                } else if (MODE == 1) {
                    float2 r = *(const float2*)(resid + (size_t)m * H + n);
                    *(float2*)(g_x1 + (size_t)m * H + n) =
                        make_float2(c0 + r.x, c1 + r.y);
                } else if (MODE == 2) {
                    *(float2*)(g_act + (size_t)(e * T + m) * F + n) = make_float2(c0, c1);
                } else if (MODE == 3) {
                    float* dst = g_act + (size_t)(e * T + m) * F + n;
                    float2 h3 = *(const float2*)dst;
                    float s0 = 1.f / (1.f + __expf(-c0));
                    float s1 = 1.f / (1.f + __expf(-c1));
                    *(float2*)dst = make_float2(c0 * s0 * h3.x, c1 * s1 * h3.y);
                } else {
                    *(float2*)(g_y + (size_t)(e * T + m) * H + n) = make_float2(c0, c1);
                }
            }
        }
    }
}

__global__ void rope_kernel(const int* __restrict__ pos) {
    int t = blockIdx.x;
    int h = threadIdx.x >> 5, d = threadIdx.x & 31;
    float p = (float)pos[t];
    float inv = powf(10000.f, -(float)d / 32.f);
    float ang = p * inv;
    float c, s;
    sincosf(ang, &s, &c);
    float* base = g_qkv + (size_t)t * QKVN + h * HD;
    float x1 = base[d], x2 = base[d + 32];
    base[d]      = x1 * c - x2 * s;
    base[d + 32] = x2 * c + x1 * s;
}

// ---------------- TF32 tensor-core flash attention -------------------------
__global__ __launch_bounds__(128) void attn_tc() {
    __shared__ unsigned KVs[64][68];
    __shared__ unsigned Ps[64][68];
    int qt = (int)gridDim.x - 1 - blockIdx.x;
    int h = blockIdx.y;
    int q0 = qt * 64;
    int kvh = h >> 2;
    int tid = threadIdx.x, warp = tid >> 5, lane = tid & 31;
    int g = lane >> 2, tig = lane & 3;
    int wrow = warp * 16;
    int ldr = tid >> 1, ldk = (tid & 1) * 32;

    {
        const float* src = g_qkv + (size_t)(q0 + ldr) * QKVN + h * HD + ldk;
        #pragma unroll
        for (int i = 0; i < 32; i += 4) {
            float4 v = *(const float4*)(src + i);
            KVs[ldr][ldk+i+0] = f2tf(v.x * 0.125f);
            KVs[ldr][ldk+i+1] = f2tf(v.y * 0.125f);
            KVs[ldr][ldk+i+2] = f2tf(v.z * 0.125f);
            KVs[ldr][ldk+i+3] = f2tf(v.w * 0.125f);
        }
    }
    __syncthreads();
    unsigned qf[8][4];
    #pragma unroll
    for (int kk = 0; kk < 8; kk++) {
        qf[kk][0] = KVs[wrow + g][kk * 8 + tig];
        qf[kk][1] = KVs[wrow + g + 8][kk * 8 + tig];
        qf[kk][2] = KVs[wrow + g][kk * 8 + tig + 4];
        qf[kk][3] = KVs[wrow + g + 8][kk * 8 + tig + 4];
    }

    float m_i[2] = {-1e30f, -1e30f};
    float l_i[2] = {0.f, 0.f};
    float O[8][4];
    #pragma unroll
    for (int nt = 0; nt < 8; nt++)
        O[nt][0] = O[nt][1] = O[nt][2] = O[nt][3] = 0.f;

    for (int kt = 0; kt <= qt; kt++) {
        int k0 = kt * 64;
        __syncthreads();
        {
            const float* src = g_qkv + (size_t)(k0 + ldr) * QKVN + 1024 + kvh * HD + ldk;
            #pragma unroll
            for (int i = 0; i < 32; i += 4) {
                float4 v = *(const float4*)(src + i);
                KVs[ldr][ldk+i+0] = f2tf(v.x);
                KVs[ldr][ldk+i+1] = f2tf(v.y);
                KVs[ldr][ldk+i+2] = f2tf(v.z);
                KVs[ldr][ldk+i+3] = f2tf(v.w);
            }
        }
        __syncthreads();

        float S[8][4];
        #pragma unroll
        for (int nt = 0; nt < 8; nt++)
            S[nt][0] = S[nt][1] = S[nt][2] = S[nt][3] = 0.f;
        #pragma unroll
        for (int kk = 0; kk < 8; kk++) {
            #pragma unroll
            for (int nt = 0; nt < 8; nt++) {
                unsigned b[2] = {KVs[nt * 8 + g][kk * 8 + tig],
                                 KVs[nt * 8 + g][kk * 8 + tig + 4]};
                mma_tf32(S[nt], qf[kk], b);
            }
        }

        if (kt == qt) {
            #pragma unroll
            for (int nt = 0; nt < 8; nt++) {
                int colb = nt * 8 + 2 * tig;
                if (colb     > wrow + g)     S[nt][0] = -1e30f;
                if (colb + 1 > wrow + g)     S[nt][1] = -1e30f;
                if (colb     > wrow + g + 8) S[nt][2] = -1e30f;
                if (colb + 1 > wrow + g + 8) S[nt][3] = -1e30f;
            }
        }
        float mx0 = -1e30f, mx1 = -1e30f;
        #pragma unroll
        for (int nt = 0; nt < 8; nt++) {
            mx0 = fmaxf(mx0, fmaxf(S[nt][0], S[nt][1]));
            mx1 = fmaxf(mx1, fmaxf(S[nt][2], S[nt][3]));
        }
        #pragma unroll
        for (int o = 1; o <= 2; o <<= 1) {
            mx0 = fmaxf(mx0, __shfl_xor_sync(0xffffffffu, mx0, o));
            mx1 = fmaxf(mx1, __shfl_xor_sync(0xffffffffu, mx1, o));
        }
        float mn0 = fmaxf(m_i[0], mx0), mn1 = fmaxf(m_i[1], mx1);
        float fac0 = __expf(m_i[0] - mn0), fac1 = __expf(m_i[1] - mn1);
        float rs0 = 0.f, rs1 = 0.f;
        #pragma unroll
        for (int nt = 0; nt < 8; nt++) {
            int colb = nt * 8 + 2 * tig;
            float p00 = __expf(S[nt][0] - mn0);
            float p01 = __expf(S[nt][1] - mn0);
            float p10 = __expf(S[nt][2] - mn1);
            float p11 = __expf(S[nt][3] - mn1);
            rs0 += p00 + p01; rs1 += p10 + p11;
            Ps[wrow + g][colb]     = f2tf(p00);
            Ps[wrow + g][colb + 1] = f2tf(p01);
            Ps[wrow + g + 8][colb]     = f2tf(p10);
            Ps[wrow + g + 8][colb + 1] = f2tf(p11);
        }
        #pragma unroll
        for (int o = 1; o <= 2; o <<= 1) {
            rs0 += __shfl_xor_sync(0xffffffffu, rs0, o);
            rs1 += __shfl_xor_sync(0xffffffffu, rs1, o);
        }
        l_i[0] = l_i[0] * fac0 + rs0;
        l_i[1] = l_i[1] * fac1 + rs1;
        m_i[0] = mn0; m_i[1] = mn1;
        #pragma unroll
        for (int nt = 0; nt < 8; nt++) {
            O[nt][0] *= fac0; O[nt][1] *= fac0;
            O[nt][2] *= fac1; O[nt][3] *= fac1;
        }

        __syncthreads();
        {
            const float* src = g_qkv + (size_t)(k0 + ldr) * QKVN + 1280 + kvh * HD + ldk;
            #pragma unroll
            for (int i = 0; i < 32; i += 4) {
                float4 v = *(const float4*)(src + i);
                KVs[ldk+i+0][ldr] = f2tf(v.x);
                KVs[ldk+i+1][ldr] = f2tf(v.y);
                KVs[ldk+i+2][ldr] = f2tf(v.z);
                KVs[ldk+i+3][ldr] = f2tf(v.w);
            }
        }
        __syncthreads();
        #pragma unroll
        for (int kk = 0; kk < 8; kk++) {
            unsigned af[4] = {Ps[wrow + g][kk * 8 + tig],
                              Ps[wrow + g + 8][kk * 8 + tig],
                              Ps[wrow + g][kk * 8 + tig + 4],
                              Ps[wrow + g + 8][kk * 8 + tig + 4]};
            #pragma unroll
            for (int nt = 0; nt < 8; nt++) {
                unsigned b[2] = {KVs[nt * 8 + g][kk * 8 + tig],
                                 KVs[nt * 8 + g][kk * 8 + tig + 4]};
                mma_tf32(O[nt], af, b);
            }
        }
    }

    float inv0 = 1.f / l_i[0], inv1 = 1.f / l_i[1];
    #pragma unroll
    for (int nt = 0; nt < 8; nt++) {
        int n = h * HD + nt * 8 + 2 * tig;
        *(float2*)(g_attn + (size_t)(q0 + wrow + g) * (NH * HD) + n) =
            make_float2(O[nt][0] * inv0, O[nt][1] * inv0);
        *(float2*)(g_attn + (size_t)(q0 + wrow + g + 8) * (NH * HD) + n) =
            make_float2(O[nt][2] * inv1, O[nt][3] * inv1);
    }
}

__global__ __launch_bounds__(256) void gate_kernel(const float* __restrict__ gate_w) {
    int t = blockIdx.x;
    const float* x = g_xnorm2 + (size_t)t * H;
    int w = threadIdx.x >> 5, lane = threadIdx.x & 31;
    float s = 0.f;
    const float* gw = gate_w + (size_t)w * H;
    for (int i = lane; i < H; i += 32) s += x[i] * gw[i];
    #pragma unroll
    for (int o = 16; o; o >>= 1) s += __shfl_xor_sync(0xffffffffu, s, o);
    __shared__ float logits[NE];
    if (lane == 0) logits[w] = s;
    __syncthreads();
    if (threadIdx.x == 0) {
        float mx = logits[0];
        #pragma unroll
        for (int e = 1; e < NE; e++) mx = fmaxf(mx, logits[e]);
        float p[NE];
        #pragma unroll
        for (int e = 0; e < NE; e++) p[e] = __expf(logits[e] - mx);
        int i1 = 0;
        #pragma unroll
        for (int e = 1; e < NE; e++) if (p[e] > p[i1]) i1 = e;
        int i2 = (i1 == 0) ? 1 : 0;
        #pragma unroll
        for (int e = 0; e < NE; e++) if (e != i1 && p[e] > p[i2]) i2 = e;
        float inv = 1.f / (p[i1] + p[i2]);
        int s0 = atomicAdd(&g_cnt[i1], 1);
        g_ptok[i1 * T + s0] = t;
        g_slot[2 * t + 0] = i1 * T + s0;
        g_gatew[2 * t + 0] = p[i1] * inv;
        int s1 = atomicAdd(&g_cnt[i2], 1);
        g_ptok[i2 * T + s1] = t;
        g_slot[2 * t + 1] = i2 * T + s1;
        g_gatew[2 * t + 1] = p[i2] * inv;
    }
}

// x = x1 + g0*y0 + g1*y1; rmsnorm(x) -> out[0..T*H); x -> out[T*H..) if room.
__global__ __launch_bounds__(256) void combine_kernel(
    const float* __restrict__ w_next, float* __restrict__ out, int write_x)
{
    __shared__ float xs[H];
    int t = blockIdx.x;
    int s0 = g_slot[2 * t + 0], s1 = g_slot[2 * t + 1];
    float g0 = g_gatew[2 * t + 0], g1 = g_gatew[2 * t + 1];
    float ss = 0.f;
    for (int i = threadIdx.x; i < H; i += 256) {
        float v = g_x1[(size_t)t * H + i]
                + g0 * g_y[(size_t)s0 * H + i]
                + g1 * g_y[(size_t)s1 * H + i];
        xs[i] = v;
        if (write_x) out[(size_t)T * H + (size_t)t * H + i] = v;
        ss += v * v;
    }
    float tot = block_sum_256(ss);
    float scale = rsqrtf(tot / (float)H + EPS);
    __syncthreads();
    for (int i = threadIdx.x; i < H; i += 256)
        out[(size_t)t * H + i] = xs[i] * scale * w_next[i];
}

// ------------------------------------------------------------------- launch
extern "C" void kernel_launch(void* const* d_in, const int* in_sizes, int n_in,
                              void* d_out, int out_size)
{
    const int*   positions = nullptr;
    const float* hidden = nullptr;
    const float* w_qkv = nullptr;
    const float* w_o = nullptr;
    const float* gate_w = nullptr;
    const float* norms[3] = {nullptr, nullptr, nullptr};
    const float* big[3]   = {nullptr, nullptr, nullptr};
    int nn = 0, nb = 0;
    for (int i = 0; i < n_in; i++) {
        switch (in_sizes[i]) {
            case 2048:     positions = (const int*)d_in[i];   break;
            case 2097152:  hidden    = (const float*)d_in[i]; break;
            case 1572864:  w_qkv     = (const float*)d_in[i]; break;
            case 1048576:  w_o       = (const float*)d_in[i]; break;
            case 8192:     gate_w    = (const float*)d_in[i]; break;
            case 1024:     if (nn < 3) norms[nn++] = (const float*)d_in[i]; break;
            case 16777216: if (nb < 3) big[nb++]   = (const float*)d_in[i]; break;
            default: break;
        }
    }
    const float* norm_in   = norms[0];
    const float* norm_post = norms[1];
    const float* norm_next = norms[2];
    const float* w1 = big[0];
    const float* w2 = big[1];
    const float* w3 = big[2];
    float* out = (float*)d_out;

    int write_x = (out_size == 2 * T * H || out_size == 2 * T * H * 4) ? 1 : 0;

    zero_cnt_kernel<<<1, 32>>>();
    rmsnorm_kernel<0><<<T, 256>>>(hidden, norm_in);
    gemm_tc<0><<<dim3(QKVN / 128, T / 128), 256>>>(w_qkv, nullptr);
    rope_kernel<<<T, (NH + NKV) * 32>>>(positions);
    attn_tc<<<dim3(T / 64, NH), 128>>>();
    gemm_tc<1><<<dim3(H / 128, T / 128), 256>>>(w_o, hidden);
    rmsnorm_kernel<1><<<T, 256>>>(nullptr, norm_post);
    gate_kernel<<<T, 256>>>(gate_w);
    gemm_tc<2><<<dim3(F / 128, T / 128, NE), 256>>>(w3, nullptr);
    gemm_tc<3><<<dim3(F / 128, T / 128, NE), 256>>>(w1, nullptr);
    gemm_tc<4><<<dim3(H / 128, T / 128, NE), 256>>>(w2, nullptr);
    combine_kernel<<<T, 256>>>(norm_next, out, write_x);
}